// round 3
// baseline (speedup 1.0000x reference)
#include <cuda_runtime.h>
#include <cuda_bf16.h>
#include <cstdint>

#define B 2
#define S 2048
#define HIDDEN 896
#define NH 14
#define NKV 2
#define HD 64
#define NREP 7
#define MTOK (B*S)          // 4096 tokens

// ---------------- scratch (device globals; no allocation allowed) ----------------
__device__ float g_qlin[MTOK * HIDDEN];        // 4096 x 896
__device__ float g_klin[MTOK * (NKV*HD)];      // 4096 x 128
__device__ float g_vlin[MTOK * (NKV*HD)];      // 4096 x 128
__device__ float g_q[B * NH * S * HD];         // [b,h,s,d]
__device__ float g_k[B * NKV * S * HD];        // [b,kv,s,d]
__device__ float g_v[B * NKV * S * HD];        // [b,kv,s,d]
__device__ float g_attn[MTOK * HIDDEN];        // [b,s,h*d]

// ---------------- GEMM: C[m,n] = sum_k X[m,k]*W[n,k] + bias[n] ----------------
#define BM 64
#define BN 64
#define BKK 16

__global__ __launch_bounds__(256) void gemm_xwT(const float* __restrict__ X,
                                                const float* __restrict__ W,
                                                const float* __restrict__ bias,
                                                float* __restrict__ C,
                                                int M, int N, int K) {
    __shared__ float Xs[BKK][BM + 2];
    __shared__ float Ws[BKK][BN + 2];

    const int tid = threadIdx.x;
    const int tx = tid & 15;       // n direction
    const int ty = tid >> 4;       // m direction
    const int m0 = blockIdx.y * BM;
    const int n0 = blockIdx.x * BN;

    float acc[4][4];
#pragma unroll
    for (int i = 0; i < 4; i++)
#pragma unroll
        for (int j = 0; j < 4; j++) acc[i][j] = 0.f;

    for (int k0 = 0; k0 < K; k0 += BKK) {
#pragma unroll
        for (int i = tid; i < BM * BKK; i += 256) {
            int mm = i >> 4;
            int kk = i & 15;
            Xs[kk][mm] = X[(size_t)(m0 + mm) * K + k0 + kk];
        }
#pragma unroll
        for (int i = tid; i < BN * BKK; i += 256) {
            int nn = i >> 4;
            int kk = i & 15;
            Ws[kk][nn] = W[(size_t)(n0 + nn) * K + k0 + kk];
        }
        __syncthreads();

#pragma unroll
        for (int kk = 0; kk < BKK; kk++) {
            float xr[4], wr[4];
#pragma unroll
            for (int i = 0; i < 4; i++) xr[i] = Xs[kk][ty * 4 + i];
#pragma unroll
            for (int j = 0; j < 4; j++) wr[j] = Ws[kk][tx * 4 + j];
#pragma unroll
            for (int i = 0; i < 4; i++)
#pragma unroll
                for (int j = 0; j < 4; j++) acc[i][j] += xr[i] * wr[j];
        }
        __syncthreads();
    }

#pragma unroll
    for (int i = 0; i < 4; i++) {
        int m = m0 + ty * 4 + i;
#pragma unroll
        for (int j = 0; j < 4; j++) {
            int n = n0 + tx * 4 + j;
            float bv = bias ? bias[n] : 0.f;
            C[(size_t)m * N + n] = acc[i][j] + bv;
        }
    }
}

// ---------------- RoPE + reshape ----------------
// position == s index (reference position_ids is broadcast(arange(S))).
__global__ void rope_reshape(const float* __restrict__ qlin,
                             const float* __restrict__ klin,
                             const float* __restrict__ vlin,
                             float* __restrict__ qout,
                             float* __restrict__ kout,
                             float* __restrict__ vout) {
    int idx = blockIdx.x * blockDim.x + threadIdx.x;
    const int total = B * S * 18 * 32;
    if (idx >= total) return;
    int pair = idx & 31;
    int rest = idx >> 5;
    int head = rest % 18;
    int bs = rest / 18;
    int b = bs / S, s = bs % S;

    if (head >= 16) {
        int kvh = head - 16;
        const float* src = vlin + (size_t)bs * (NKV * HD) + kvh * HD;
        float* dst = vout + (((size_t)b * NKV + kvh) * S + s) * HD;
        dst[pair] = src[pair];
        dst[pair + 32] = src[pair + 32];
        return;
    }

    float pos = (float)s;
    const float LOG2_THETA_OVER_32 = 0.62286105580517513f;  // log2(1e6)/32
    float inv = exp2f(-(float)pair * LOG2_THETA_OVER_32);
    float f = pos * inv;
    float sn, cs;
    sincosf(f, &sn, &cs);

    if (head < 14) {
        const float* src = qlin + (size_t)bs * HIDDEN + head * HD;
        float x1 = src[pair], x2 = src[pair + 32];
        float* dst = qout + (((size_t)b * NH + head) * S + s) * HD;
        dst[pair] = x1 * cs - x2 * sn;
        dst[pair + 32] = x2 * cs + x1 * sn;
    } else {
        int kvh = head - 14;
        const float* src = klin + (size_t)bs * (NKV * HD) + kvh * HD;
        float x1 = src[pair], x2 = src[pair + 32];
        float* dst = kout + (((size_t)b * NKV + kvh) * S + s) * HD;
        dst[pair] = x1 * cs - x2 * sn;
        dst[pair + 32] = x2 * cs + x1 * sn;
    }
}

// ---------------- Flash attention v2: tf32 mma.sync ----------------
// grid (S/64, NH, B), 128 threads = 4 warps; warp w owns q rows [w*16, w*16+16).
// smem: Ks[64][68] (tf32), Vs[64][72] (tf32), Ps[64][68] (tf32)  — uint32 words.

#define KS_STRIDE 68
#define VS_STRIDE 72
#define PS_STRIDE 68
#define ATTN_SMEM ((64*KS_STRIDE + 64*VS_STRIDE + 64*PS_STRIDE) * 4)

__device__ __forceinline__ uint32_t f2tf32(float x) {
    uint32_t r;
    asm("cvt.rna.tf32.f32 %0, %1;" : "=r"(r) : "f"(x));
    return r;
}

__device__ __forceinline__ void mma_tf32(float* d, const uint32_t* a, uint32_t b0, uint32_t b1) {
    asm volatile(
        "mma.sync.aligned.m16n8k8.row.col.f32.tf32.tf32.f32 "
        "{%0,%1,%2,%3}, {%4,%5,%6,%7}, {%8,%9}, {%0,%1,%2,%3};\n"
        : "+f"(d[0]), "+f"(d[1]), "+f"(d[2]), "+f"(d[3])
        : "r"(a[0]), "r"(a[1]), "r"(a[2]), "r"(a[3]), "r"(b0), "r"(b1));
}

__global__ __launch_bounds__(128, 4) void attn_kernel(const float* __restrict__ Q,
                                                      const float* __restrict__ K,
                                                      const float* __restrict__ V,
                                                      float* __restrict__ O) {
    extern __shared__ uint32_t sm_u[];
    uint32_t* Ks = sm_u;                      // [64][68]
    uint32_t* Vs = Ks + 64 * KS_STRIDE;       // [64][72]
    uint32_t* Ps = Vs + 64 * VS_STRIDE;       // [64][68]

    const int qt = blockIdx.x;
    const int h = blockIdx.y;
    const int b = blockIdx.z;
    const int kvh = h / NREP;
    const int tid = threadIdx.x;
    const int w = tid >> 5;
    const int lane = tid & 31;
    const int lg = lane >> 2;     // group id (0..7)
    const int lt = lane & 3;      // thread in group (0..3)

    const float* Qb = Q + (((size_t)b * NH + h) * S + (size_t)qt * 64) * HD;
    const float* Kb = K + (((size_t)b * NKV + kvh) * S) * HD;
    const float* Vb = V + (((size_t)b * NKV + kvh) * S) * HD;

    // Q fragments: rows w*16 + lg (+8), cols ks*8 + lt (+4). Scale folded in.
    const float scale = 0.125f;   // 1/sqrt(64)
    uint32_t aq[8][4];
    {
        const int r0 = w * 16 + lg;
#pragma unroll
        for (int ks = 0; ks < 8; ks++) {
            int c0 = ks * 8 + lt;
            aq[ks][0] = f2tf32(scale * Qb[(size_t)r0 * HD + c0]);
            aq[ks][1] = f2tf32(scale * Qb[(size_t)(r0 + 8) * HD + c0]);
            aq[ks][2] = f2tf32(scale * Qb[(size_t)r0 * HD + c0 + 4]);
            aq[ks][3] = f2tf32(scale * Qb[(size_t)(r0 + 8) * HD + c0 + 4]);
        }
    }

    float o[8][4];
#pragma unroll
    for (int n = 0; n < 8; n++)
#pragma unroll
        for (int j = 0; j < 4; j++) o[n][j] = 0.f;
    float m0 = -1e30f, m1 = -1e30f, l0 = 0.f, l1 = 0.f;

    for (int kt = 0; kt <= qt; kt++) {
        __syncthreads();
        // stage K,V tile (convert to tf32)
        for (int i = tid; i < 64 * 64; i += 128) {
            int r = i >> 6, d = i & 63;
            Ks[r * KS_STRIDE + d] = f2tf32(Kb[((size_t)kt * 64 + r) * HD + d]);
            Vs[r * VS_STRIDE + d] = f2tf32(Vb[((size_t)kt * 64 + r) * HD + d]);
        }
        __syncthreads();

        // ---- QK^T: c[n] = Q(16x64) * K^T -> 16x64 scores ----
        float c[8][4];
#pragma unroll
        for (int n = 0; n < 8; n++) {
#pragma unroll
            for (int j = 0; j < 4; j++) c[n][j] = 0.f;
#pragma unroll
            for (int ks = 0; ks < 8; ks++) {
                const uint32_t* krow = Ks + (n * 8 + lg) * KS_STRIDE + ks * 8 + lt;
                mma_tf32(c[n], aq[ks], krow[0], krow[4]);
            }
        }

        // ---- causal mask on diagonal tile ----
        if (kt == qt) {
            const int row0 = qt * 64 + w * 16 + lg;
#pragma unroll
            for (int n = 0; n < 8; n++) {
                int col = kt * 64 + n * 8 + 2 * lt;
                if (col > row0)         c[n][0] = -1e30f;
                if (col + 1 > row0)     c[n][1] = -1e30f;
                if (col > row0 + 8)     c[n][2] = -1e30f;
                if (col + 1 > row0 + 8) c[n][3] = -1e30f;
            }
        }

        // ---- online softmax ----
        float mx0 = -1e30f, mx1 = -1e30f;
#pragma unroll
        for (int n = 0; n < 8; n++) {
            mx0 = fmaxf(mx0, fmaxf(c[n][0], c[n][1]));
            mx1 = fmaxf(mx1, fmaxf(c[n][2], c[n][3]));
        }
        mx0 = fmaxf(mx0, __shfl_xor_sync(0xffffffffu, mx0, 1));
        mx0 = fmaxf(mx0, __shfl_xor_sync(0xffffffffu, mx0, 2));
        mx1 = fmaxf(mx1, __shfl_xor_sync(0xffffffffu, mx1, 1));
        mx1 = fmaxf(mx1, __shfl_xor_sync(0xffffffffu, mx1, 2));

        float mn0 = fmaxf(m0, mx0);
        float mn1 = fmaxf(m1, mx1);
        float corr0 = __expf(m0 - mn0);
        float corr1 = __expf(m1 - mn1);

        float sum0 = 0.f, sum1 = 0.f;
        {
            const int r0 = w * 16 + lg;
            uint32_t* p0row = Ps + r0 * PS_STRIDE + 2 * lt;
            uint32_t* p1row = Ps + (r0 + 8) * PS_STRIDE + 2 * lt;
#pragma unroll
            for (int n = 0; n < 8; n++) {
                float p00 = __expf(c[n][0] - mn0);
                float p01 = __expf(c[n][1] - mn0);
                float p10 = __expf(c[n][2] - mn1);
                float p11 = __expf(c[n][3] - mn1);
                sum0 += p00 + p01;
                sum1 += p10 + p11;
                uint2 v0 = make_uint2(f2tf32(p00), f2tf32(p01));
                uint2 v1 = make_uint2(f2tf32(p10), f2tf32(p11));
                *reinterpret_cast<uint2*>(p0row + n * 8) = v0;
                *reinterpret_cast<uint2*>(p1row + n * 8) = v1;
            }
        }
        sum0 += __shfl_xor_sync(0xffffffffu, sum0, 1);
        sum0 += __shfl_xor_sync(0xffffffffu, sum0, 2);
        sum1 += __shfl_xor_sync(0xffffffffu, sum1, 1);
        sum1 += __shfl_xor_sync(0xffffffffu, sum1, 2);

        l0 = l0 * corr0 + sum0;
        l1 = l1 * corr1 + sum1;
        m0 = mn0;
        m1 = mn1;

        // rescale accumulators
#pragma unroll
        for (int n = 0; n < 8; n++) {
            o[n][0] *= corr0;
            o[n][1] *= corr0;
            o[n][2] *= corr1;
            o[n][3] *= corr1;
        }
        __syncwarp();

        // ---- P*V: o += P(16x64) * V(64x64) ----
#pragma unroll
        for (int ks = 0; ks < 8; ks++) {
            uint32_t pa[4];
            const uint32_t* prow = Ps + (w * 16 + lg) * PS_STRIDE + ks * 8 + lt;
            pa[0] = prow[0];
            pa[1] = prow[8 * PS_STRIDE];
            pa[2] = prow[4];
            pa[3] = prow[8 * PS_STRIDE + 4];
#pragma unroll
            for (int n = 0; n < 8; n++) {
                const uint32_t* vrow = Vs + (ks * 8 + lt) * VS_STRIDE + n * 8 + lg;
                mma_tf32(o[n], pa, vrow[0], vrow[4 * VS_STRIDE]);
            }
        }
    }

    // ---- write normalized output to [b, s, h*64 + d] ----
    {
        float inv0 = 1.f / l0;
        float inv1 = 1.f / l1;
        const int r0 = qt * 64 + w * 16 + lg;
        float* out0 = O + ((size_t)b * S + r0) * HIDDEN + h * HD + 2 * lt;
        float* out1 = O + ((size_t)b * S + r0 + 8) * HIDDEN + h * HD + 2 * lt;
#pragma unroll
        for (int n = 0; n < 8; n++) {
            *reinterpret_cast<float2*>(out0 + n * 8) = make_float2(o[n][0] * inv0, o[n][1] * inv0);
            *reinterpret_cast<float2*>(out1 + n * 8) = make_float2(o[n][2] * inv1, o[n][3] * inv1);
        }
    }
}

// ---------------- launch ----------------
extern "C" void kernel_launch(void* const* d_in, const int* in_sizes, int n_in,
                              void* d_out, int out_size) {
    const float* hs = (const float*)d_in[0];
    const float* Wq = (const float*)d_in[2];
    const float* bq = (const float*)d_in[3];
    const float* Wk = (const float*)d_in[4];
    const float* bk = (const float*)d_in[5];
    const float* Wv = (const float*)d_in[6];
    const float* bv = (const float*)d_in[7];
    const float* Wo = (const float*)d_in[8];
    float* out = (float*)d_out;

    float *qlin, *klin, *vlin, *q, *k, *v, *attn;
    cudaGetSymbolAddress((void**)&qlin, g_qlin);
    cudaGetSymbolAddress((void**)&klin, g_klin);
    cudaGetSymbolAddress((void**)&vlin, g_vlin);
    cudaGetSymbolAddress((void**)&q, g_q);
    cudaGetSymbolAddress((void**)&k, g_k);
    cudaGetSymbolAddress((void**)&v, g_v);
    cudaGetSymbolAddress((void**)&attn, g_attn);

    static bool attr_set = false;
    if (!attr_set) {
        cudaFuncSetAttribute(attn_kernel, cudaFuncAttributeMaxDynamicSharedMemorySize, ATTN_SMEM);
        attr_set = true;
    }

    // QKV projections
    gemm_xwT<<<dim3(HIDDEN / BN, MTOK / BM), 256>>>(hs, Wq, bq, qlin, MTOK, HIDDEN, HIDDEN);
    gemm_xwT<<<dim3((NKV * HD) / BN, MTOK / BM), 256>>>(hs, Wk, bk, klin, MTOK, NKV * HD, HIDDEN);
    gemm_xwT<<<dim3((NKV * HD) / BN, MTOK / BM), 256>>>(hs, Wv, bv, vlin, MTOK, NKV * HD, HIDDEN);

    // RoPE + layout
    {
        int total = B * S * 18 * 32;
        rope_reshape<<<(total + 255) / 256, 256>>>(qlin, klin, vlin, q, k, v);
    }

    // attention (tf32 tensor core)
    attn_kernel<<<dim3(S / 64, NH, B), 128, ATTN_SMEM>>>(q, k, v, attn);

    // output projection
    gemm_xwT<<<dim3(HIDDEN / BN, MTOK / BM), 256>>>(attn, Wo, nullptr, out, MTOK, HIDDEN, HIDDEN);
}

// round 4
// speedup vs baseline: 2.1008x; 2.1008x over previous
#include <cuda_runtime.h>
#include <cuda_bf16.h>
#include <cstdint>

#define B 2
#define S 2048
#define HIDDEN 896
#define NH 14
#define NKV 2
#define HD 64
#define NREP 7
#define MTOK (B*S)          // 4096 tokens

// ---------------- scratch (device globals; no allocation allowed) ----------------
__device__ float g_qlin[MTOK * HIDDEN];        // 4096 x 896
__device__ float g_klin[MTOK * (NKV*HD)];      // 4096 x 128
__device__ float g_vlin[MTOK * (NKV*HD)];      // 4096 x 128
__device__ float g_q[B * NH * S * HD];         // [b,h,s,d]
__device__ float g_k[B * NKV * S * HD];        // [b,kv,s,d]
__device__ float g_v[B * NKV * S * HD];        // [b,kv,s,d]
__device__ float g_attn[MTOK * HIDDEN];        // [b,s,h*d]

// ---------------- common mma helpers ----------------
__device__ __forceinline__ uint32_t f2tf32(float x) {
    uint32_t r;
    asm("cvt.rna.tf32.f32 %0, %1;" : "=r"(r) : "f"(x));
    return r;
}

__device__ __forceinline__ void mma_tf32(float* d, const uint32_t* a, uint32_t b0, uint32_t b1) {
    asm volatile(
        "mma.sync.aligned.m16n8k8.row.col.f32.tf32.tf32.f32 "
        "{%0,%1,%2,%3}, {%4,%5,%6,%7}, {%8,%9}, {%0,%1,%2,%3};\n"
        : "+f"(d[0]), "+f"(d[1]), "+f"(d[2]), "+f"(d[3])
        : "r"(a[0]), "r"(a[1]), "r"(a[2]), "r"(a[3]), "r"(b0), "r"(b1));
}

// ---------------- GEMM via tf32 mma with hi/lo split (near-fp32 accuracy) ----------
// C[m,n] = sum_k X[m,k]*W[n,k] + bias[n]
// Tiles: BM=64, BN=64, BK=32. 128 threads = 4 warps, warp w computes rows [w*16,w*16+16) x 64 cols.
#define GSTRIDE 36   // 36 mod 32 = 4 -> bank(row,col) = 4*lg + lt, conflict-free for mma frags

__global__ __launch_bounds__(128) void gemm_tf32(const float* __restrict__ X,
                                                 const float* __restrict__ W,
                                                 const float* __restrict__ bias,
                                                 float* __restrict__ C,
                                                 int M, int N, int K) {
    __shared__ uint32_t Xhi[64 * GSTRIDE];
    __shared__ uint32_t Xlo[64 * GSTRIDE];
    __shared__ uint32_t Whi[64 * GSTRIDE];
    __shared__ uint32_t Wlo[64 * GSTRIDE];

    const int tid = threadIdx.x;
    const int w = tid >> 5;
    const int lane = tid & 31;
    const int lg = lane >> 2;   // 0..7
    const int lt = lane & 3;    // 0..3
    const int m0 = blockIdx.y * 64;
    const int n0 = blockIdx.x * 64;

    float c[8][4];
#pragma unroll
    for (int n = 0; n < 8; n++)
#pragma unroll
        for (int j = 0; j < 4; j++) c[n][j] = 0.f;

    for (int k0 = 0; k0 < K; k0 += 32) {
        __syncthreads();
        // stage 64x32 X tile and 64x32 W tile, split hi/lo. 512 float4 per tile, 4 per thread.
#pragma unroll
        for (int j = 0; j < 4; j++) {
            int idx = tid * 4 + j;
            int row = idx >> 3;         // 8 float4 per row
            int f4c = idx & 7;
            float4 xv = *reinterpret_cast<const float4*>(&X[(size_t)(m0 + row) * K + k0 + f4c * 4]);
            float4 wv = *reinterpret_cast<const float4*>(&W[(size_t)(n0 + row) * K + k0 + f4c * 4]);
            uint4 xh, xl, wh, wl;
            xh.x = f2tf32(xv.x); xl.x = f2tf32(xv.x - __uint_as_float(xh.x));
            xh.y = f2tf32(xv.y); xl.y = f2tf32(xv.y - __uint_as_float(xh.y));
            xh.z = f2tf32(xv.z); xl.z = f2tf32(xv.z - __uint_as_float(xh.z));
            xh.w = f2tf32(xv.w); xl.w = f2tf32(xv.w - __uint_as_float(xh.w));
            wh.x = f2tf32(wv.x); wl.x = f2tf32(wv.x - __uint_as_float(wh.x));
            wh.y = f2tf32(wv.y); wl.y = f2tf32(wv.y - __uint_as_float(wh.y));
            wh.z = f2tf32(wv.z); wl.z = f2tf32(wv.z - __uint_as_float(wh.z));
            wh.w = f2tf32(wv.w); wl.w = f2tf32(wv.w - __uint_as_float(wh.w));
            int so = row * GSTRIDE + f4c * 4;
            *reinterpret_cast<uint4*>(&Xhi[so]) = xh;
            *reinterpret_cast<uint4*>(&Xlo[so]) = xl;
            *reinterpret_cast<uint4*>(&Whi[so]) = wh;
            *reinterpret_cast<uint4*>(&Wlo[so]) = wl;
        }
        __syncthreads();

#pragma unroll
        for (int ks = 0; ks < 4; ks++) {
            uint32_t ah[4], al[4];
            int ab = (w * 16 + lg) * GSTRIDE + ks * 8 + lt;
            ah[0] = Xhi[ab];                ah[1] = Xhi[ab + 8 * GSTRIDE];
            ah[2] = Xhi[ab + 4];            ah[3] = Xhi[ab + 8 * GSTRIDE + 4];
            al[0] = Xlo[ab];                al[1] = Xlo[ab + 8 * GSTRIDE];
            al[2] = Xlo[ab + 4];            al[3] = Xlo[ab + 8 * GSTRIDE + 4];
#pragma unroll
            for (int nf = 0; nf < 8; nf++) {
                int bb = (nf * 8 + lg) * GSTRIDE + ks * 8 + lt;
                uint32_t bh0 = Whi[bb], bh1 = Whi[bb + 4];
                uint32_t bl0 = Wlo[bb], bl1 = Wlo[bb + 4];
                mma_tf32(c[nf], ah, bh0, bh1);
                mma_tf32(c[nf], ah, bl0, bl1);
                mma_tf32(c[nf], al, bh0, bh1);
            }
        }
    }

    // epilogue
    const int row = m0 + w * 16 + lg;
#pragma unroll
    for (int nf = 0; nf < 8; nf++) {
        int col = n0 + nf * 8 + 2 * lt;
        float bv0 = bias ? bias[col] : 0.f;
        float bv1 = bias ? bias[col + 1] : 0.f;
        *reinterpret_cast<float2*>(&C[(size_t)row * N + col]) =
            make_float2(c[nf][0] + bv0, c[nf][1] + bv1);
        *reinterpret_cast<float2*>(&C[(size_t)(row + 8) * N + col]) =
            make_float2(c[nf][2] + bv0, c[nf][3] + bv1);
    }
}

// ---------------- RoPE + reshape ----------------
// position == s index (reference position_ids is broadcast(arange(S))).
__global__ void rope_reshape(const float* __restrict__ qlin,
                             const float* __restrict__ klin,
                             const float* __restrict__ vlin,
                             float* __restrict__ qout,
                             float* __restrict__ kout,
                             float* __restrict__ vout) {
    int idx = blockIdx.x * blockDim.x + threadIdx.x;
    const int total = B * S * 18 * 32;
    if (idx >= total) return;
    int pair = idx & 31;
    int rest = idx >> 5;
    int head = rest % 18;
    int bs = rest / 18;
    int b = bs / S, s = bs % S;

    if (head >= 16) {
        int kvh = head - 16;
        const float* src = vlin + (size_t)bs * (NKV * HD) + kvh * HD;
        float* dst = vout + (((size_t)b * NKV + kvh) * S + s) * HD;
        dst[pair] = src[pair];
        dst[pair + 32] = src[pair + 32];
        return;
    }

    float pos = (float)s;
    const float LOG2_THETA_OVER_32 = 0.62286105580517513f;  // log2(1e6)/32
    float inv = exp2f(-(float)pair * LOG2_THETA_OVER_32);
    float f = pos * inv;
    float sn, cs;
    sincosf(f, &sn, &cs);

    if (head < 14) {
        const float* src = qlin + (size_t)bs * HIDDEN + head * HD;
        float x1 = src[pair], x2 = src[pair + 32];
        float* dst = qout + (((size_t)b * NH + head) * S + s) * HD;
        dst[pair] = x1 * cs - x2 * sn;
        dst[pair + 32] = x2 * cs + x1 * sn;
    } else {
        int kvh = head - 14;
        const float* src = klin + (size_t)bs * (NKV * HD) + kvh * HD;
        float x1 = src[pair], x2 = src[pair + 32];
        float* dst = kout + (((size_t)b * NKV + kvh) * S + s) * HD;
        dst[pair] = x1 * cs - x2 * sn;
        dst[pair + 32] = x2 * cs + x1 * sn;
    }
}

// ---------------- Flash attention: tf32 mma.sync ----------------
#define KS_STRIDE 68
#define VS_STRIDE 72
#define PS_STRIDE 68
#define ATTN_SMEM ((64*KS_STRIDE + 64*VS_STRIDE + 64*PS_STRIDE) * 4)

__global__ __launch_bounds__(128, 4) void attn_kernel(const float* __restrict__ Q,
                                                      const float* __restrict__ K,
                                                      const float* __restrict__ V,
                                                      float* __restrict__ O) {
    extern __shared__ uint32_t sm_u[];
    uint32_t* Ks = sm_u;                      // [64][68]
    uint32_t* Vs = Ks + 64 * KS_STRIDE;       // [64][72]
    uint32_t* Ps = Vs + 64 * VS_STRIDE;       // [64][68]

    const int qt = blockIdx.x;
    const int h = blockIdx.y;
    const int b = blockIdx.z;
    const int kvh = h / NREP;
    const int tid = threadIdx.x;
    const int w = tid >> 5;
    const int lane = tid & 31;
    const int lg = lane >> 2;
    const int lt = lane & 3;

    const float* Qb = Q + (((size_t)b * NH + h) * S + (size_t)qt * 64) * HD;
    const float* Kb = K + (((size_t)b * NKV + kvh) * S) * HD;
    const float* Vb = V + (((size_t)b * NKV + kvh) * S) * HD;

    const float scale = 0.125f;   // 1/sqrt(64)
    uint32_t aq[8][4];
    {
        const int r0 = w * 16 + lg;
#pragma unroll
        for (int ks = 0; ks < 8; ks++) {
            int c0 = ks * 8 + lt;
            aq[ks][0] = f2tf32(scale * Qb[(size_t)r0 * HD + c0]);
            aq[ks][1] = f2tf32(scale * Qb[(size_t)(r0 + 8) * HD + c0]);
            aq[ks][2] = f2tf32(scale * Qb[(size_t)r0 * HD + c0 + 4]);
            aq[ks][3] = f2tf32(scale * Qb[(size_t)(r0 + 8) * HD + c0 + 4]);
        }
    }

    float o[8][4];
#pragma unroll
    for (int n = 0; n < 8; n++)
#pragma unroll
        for (int j = 0; j < 4; j++) o[n][j] = 0.f;
    float m0 = -1e30f, m1 = -1e30f, l0 = 0.f, l1 = 0.f;

    for (int kt = 0; kt <= qt; kt++) {
        __syncthreads();
        for (int i = tid; i < 64 * 64; i += 128) {
            int r = i >> 6, d = i & 63;
            Ks[r * KS_STRIDE + d] = f2tf32(Kb[((size_t)kt * 64 + r) * HD + d]);
            Vs[r * VS_STRIDE + d] = f2tf32(Vb[((size_t)kt * 64 + r) * HD + d]);
        }
        __syncthreads();

        float c[8][4];
#pragma unroll
        for (int n = 0; n < 8; n++) {
#pragma unroll
            for (int j = 0; j < 4; j++) c[n][j] = 0.f;
#pragma unroll
            for (int ks = 0; ks < 8; ks++) {
                const uint32_t* krow = Ks + (n * 8 + lg) * KS_STRIDE + ks * 8 + lt;
                mma_tf32(c[n], aq[ks], krow[0], krow[4]);
            }
        }

        if (kt == qt) {
            const int row0 = qt * 64 + w * 16 + lg;
#pragma unroll
            for (int n = 0; n < 8; n++) {
                int col = kt * 64 + n * 8 + 2 * lt;
                if (col > row0)         c[n][0] = -1e30f;
                if (col + 1 > row0)     c[n][1] = -1e30f;
                if (col > row0 + 8)     c[n][2] = -1e30f;
                if (col + 1 > row0 + 8) c[n][3] = -1e30f;
            }
        }

        float mx0 = -1e30f, mx1 = -1e30f;
#pragma unroll
        for (int n = 0; n < 8; n++) {
            mx0 = fmaxf(mx0, fmaxf(c[n][0], c[n][1]));
            mx1 = fmaxf(mx1, fmaxf(c[n][2], c[n][3]));
        }
        mx0 = fmaxf(mx0, __shfl_xor_sync(0xffffffffu, mx0, 1));
        mx0 = fmaxf(mx0, __shfl_xor_sync(0xffffffffu, mx0, 2));
        mx1 = fmaxf(mx1, __shfl_xor_sync(0xffffffffu, mx1, 1));
        mx1 = fmaxf(mx1, __shfl_xor_sync(0xffffffffu, mx1, 2));

        float mn0 = fmaxf(m0, mx0);
        float mn1 = fmaxf(m1, mx1);
        float corr0 = __expf(m0 - mn0);
        float corr1 = __expf(m1 - mn1);

        float sum0 = 0.f, sum1 = 0.f;
        {
            const int r0 = w * 16 + lg;
            uint32_t* p0row = Ps + r0 * PS_STRIDE + 2 * lt;
            uint32_t* p1row = Ps + (r0 + 8) * PS_STRIDE + 2 * lt;
#pragma unroll
            for (int n = 0; n < 8; n++) {
                float p00 = __expf(c[n][0] - mn0);
                float p01 = __expf(c[n][1] - mn0);
                float p10 = __expf(c[n][2] - mn1);
                float p11 = __expf(c[n][3] - mn1);
                sum0 += p00 + p01;
                sum1 += p10 + p11;
                uint2 v0 = make_uint2(f2tf32(p00), f2tf32(p01));
                uint2 v1 = make_uint2(f2tf32(p10), f2tf32(p11));
                *reinterpret_cast<uint2*>(p0row + n * 8) = v0;
                *reinterpret_cast<uint2*>(p1row + n * 8) = v1;
            }
        }
        sum0 += __shfl_xor_sync(0xffffffffu, sum0, 1);
        sum0 += __shfl_xor_sync(0xffffffffu, sum0, 2);
        sum1 += __shfl_xor_sync(0xffffffffu, sum1, 1);
        sum1 += __shfl_xor_sync(0xffffffffu, sum1, 2);

        l0 = l0 * corr0 + sum0;
        l1 = l1 * corr1 + sum1;
        m0 = mn0;
        m1 = mn1;

#pragma unroll
        for (int n = 0; n < 8; n++) {
            o[n][0] *= corr0;
            o[n][1] *= corr0;
            o[n][2] *= corr1;
            o[n][3] *= corr1;
        }
        __syncwarp();

#pragma unroll
        for (int ks = 0; ks < 8; ks++) {
            uint32_t pa[4];
            const uint32_t* prow = Ps + (w * 16 + lg) * PS_STRIDE + ks * 8 + lt;
            pa[0] = prow[0];
            pa[1] = prow[8 * PS_STRIDE];
            pa[2] = prow[4];
            pa[3] = prow[8 * PS_STRIDE + 4];
#pragma unroll
            for (int n = 0; n < 8; n++) {
                const uint32_t* vrow = Vs + (ks * 8 + lt) * VS_STRIDE + n * 8 + lg;
                mma_tf32(o[n], pa, vrow[0], vrow[4 * VS_STRIDE]);
            }
        }
    }

    {
        float inv0 = 1.f / l0;
        float inv1 = 1.f / l1;
        const int r0 = qt * 64 + w * 16 + lg;
        float* out0 = O + ((size_t)b * S + r0) * HIDDEN + h * HD + 2 * lt;
        float* out1 = O + ((size_t)b * S + r0 + 8) * HIDDEN + h * HD + 2 * lt;
#pragma unroll
        for (int n = 0; n < 8; n++) {
            *reinterpret_cast<float2*>(out0 + n * 8) = make_float2(o[n][0] * inv0, o[n][1] * inv0);
            *reinterpret_cast<float2*>(out1 + n * 8) = make_float2(o[n][2] * inv1, o[n][3] * inv1);
        }
    }
}

// ---------------- launch ----------------
extern "C" void kernel_launch(void* const* d_in, const int* in_sizes, int n_in,
                              void* d_out, int out_size) {
    const float* hs = (const float*)d_in[0];
    const float* Wq = (const float*)d_in[2];
    const float* bq = (const float*)d_in[3];
    const float* Wk = (const float*)d_in[4];
    const float* bk = (const float*)d_in[5];
    const float* Wv = (const float*)d_in[6];
    const float* bv = (const float*)d_in[7];
    const float* Wo = (const float*)d_in[8];
    float* out = (float*)d_out;

    float *qlin, *klin, *vlin, *q, *k, *v, *attn;
    cudaGetSymbolAddress((void**)&qlin, g_qlin);
    cudaGetSymbolAddress((void**)&klin, g_klin);
    cudaGetSymbolAddress((void**)&vlin, g_vlin);
    cudaGetSymbolAddress((void**)&q, g_q);
    cudaGetSymbolAddress((void**)&k, g_k);
    cudaGetSymbolAddress((void**)&v, g_v);
    cudaGetSymbolAddress((void**)&attn, g_attn);

    static bool attr_set = false;
    if (!attr_set) {
        cudaFuncSetAttribute(attn_kernel, cudaFuncAttributeMaxDynamicSharedMemorySize, ATTN_SMEM);
        attr_set = true;
    }

    // QKV projections (tf32 split mma)
    gemm_tf32<<<dim3(HIDDEN / 64, MTOK / 64), 128>>>(hs, Wq, bq, qlin, MTOK, HIDDEN, HIDDEN);
    gemm_tf32<<<dim3((NKV * HD) / 64, MTOK / 64), 128>>>(hs, Wk, bk, klin, MTOK, NKV * HD, HIDDEN);
    gemm_tf32<<<dim3((NKV * HD) / 64, MTOK / 64), 128>>>(hs, Wv, bv, vlin, MTOK, NKV * HD, HIDDEN);

    // RoPE + layout
    {
        int total = B * S * 18 * 32;
        rope_reshape<<<(total + 255) / 256, 256>>>(qlin, klin, vlin, q, k, v);
    }

    // attention (tf32 tensor core)
    attn_kernel<<<dim3(S / 64, NH, B), 128, ATTN_SMEM>>>(q, k, v, attn);

    // output projection
    gemm_tf32<<<dim3(HIDDEN / 64, MTOK / 64), 128>>>(attn, Wo, nullptr, out, MTOK, HIDDEN, HIDDEN);
}

// round 5
// speedup vs baseline: 3.0439x; 1.4489x over previous
#include <cuda_runtime.h>
#include <cuda_bf16.h>
#include <cstdint>

#define B 2
#define S 2048
#define HIDDEN 896
#define NH 14
#define NKV 2
#define HD 64
#define NREP 7
#define MTOK (B*S)          // 4096 tokens

// ---------------- scratch (device globals; no allocation allowed) ----------------
__device__ float g_q[B * NH * S * HD];         // [b,h,s,d]
__device__ float g_k[B * NKV * S * HD];        // [b,kv,s,d]
__device__ float g_v[B * NKV * S * HD];        // [b,kv,s,d]
__device__ float g_attn[MTOK * HIDDEN];        // [b,s,h*d]
__device__ float2 g_rope[S * 32];              // cos,sin per (s, freq)

// ---------------- helpers ----------------
__device__ __forceinline__ uint32_t f2tf32(float x) {
    uint32_t r;
    asm("cvt.rna.tf32.f32 %0, %1;" : "=r"(r) : "f"(x));
    return r;
}

__device__ __forceinline__ void mma_tf32(float* d, const uint32_t* a, uint32_t b0, uint32_t b1) {
    asm volatile(
        "mma.sync.aligned.m16n8k8.row.col.f32.tf32.tf32.f32 "
        "{%0,%1,%2,%3}, {%4,%5,%6,%7}, {%8,%9}, {%0,%1,%2,%3};\n"
        : "+f"(d[0]), "+f"(d[1]), "+f"(d[2]), "+f"(d[3])
        : "r"(a[0]), "r"(a[1]), "r"(a[2]), "r"(a[3]), "r"(b0), "r"(b1));
}

__device__ __forceinline__ void mma_bf16(float* d, const uint32_t* a, uint32_t b0, uint32_t b1) {
    asm volatile(
        "mma.sync.aligned.m16n8k16.row.col.f32.bf16.bf16.f32 "
        "{%0,%1,%2,%3}, {%4,%5,%6,%7}, {%8,%9}, {%0,%1,%2,%3};\n"
        : "+f"(d[0]), "+f"(d[1]), "+f"(d[2]), "+f"(d[3])
        : "r"(a[0]), "r"(a[1]), "r"(a[2]), "r"(a[3]), "r"(b0), "r"(b1));
}

// pack two floats into bf16x2 hi word + bf16x2 lo (residual) word
__device__ __forceinline__ void split2(float x0, float x1, uint32_t& hi, uint32_t& lo) {
    asm("cvt.rn.bf16x2.f32 %0, %1, %2;" : "=r"(hi) : "f"(x1), "f"(x0));
    float h0 = __uint_as_float(hi << 16);
    float h1 = __uint_as_float(hi & 0xffff0000u);
    float r0 = x0 - h0;
    float r1 = x1 - h1;
    asm("cvt.rn.bf16x2.f32 %0, %1, %2;" : "=r"(lo) : "f"(r1), "f"(r0));
}

// ---------------- rope table ----------------
__global__ void build_rope(float2* tab) {
    int idx = blockIdx.x * blockDim.x + threadIdx.x;   // [0, S*32)
    int s = idx >> 5, i = idx & 31;
    const float LOG2_THETA_OVER_32 = 0.62286105580517513f;  // log2(1e6)/32
    float inv = exp2f(-(float)i * LOG2_THETA_OVER_32);
    float sn, cs;
    sincosf((float)s * inv, &sn, &cs);
    tab[idx] = make_float2(cs, sn);
}

// ---------------- GEMM core: bf16 hi/lo split, 64x64 tile, BK=32, 128 threads ----
#define GSTRIDE 20   // words per staged row (16 data + 4 pad); conflict-free frags

// computes c[8][4] = X[m0:m0+64, :K] * Wsel[0:64, :K]^T  fragments for this thread
__device__ __forceinline__ void gemm_core(const float* __restrict__ X,
                                          const float* __restrict__ Wsel,
                                          int K, int m0, float c[8][4],
                                          uint32_t* sm, int tid, int w, int lg, int lt) {
    uint32_t* Xhi = sm;
    uint32_t* Xlo = sm + 64 * GSTRIDE;
    uint32_t* Whi = sm + 2 * 64 * GSTRIDE;
    uint32_t* Wlo = sm + 3 * 64 * GSTRIDE;

#pragma unroll
    for (int n = 0; n < 8; n++)
#pragma unroll
        for (int j = 0; j < 4; j++) c[n][j] = 0.f;

    for (int k0 = 0; k0 < K; k0 += 32) {
        __syncthreads();
#pragma unroll
        for (int j = 0; j < 4; j++) {
            int idx = tid * 4 + j;
            int row = idx >> 3;         // 8 float4 per 32-wide row
            int f4c = idx & 7;
            float4 xv = *reinterpret_cast<const float4*>(&X[(size_t)(m0 + row) * K + k0 + f4c * 4]);
            float4 wv = *reinterpret_cast<const float4*>(&Wsel[(size_t)row * K + k0 + f4c * 4]);
            uint2 xh, xl, wh, wl;
            split2(xv.x, xv.y, xh.x, xl.x);
            split2(xv.z, xv.w, xh.y, xl.y);
            split2(wv.x, wv.y, wh.x, wl.x);
            split2(wv.z, wv.w, wh.y, wl.y);
            int so = row * GSTRIDE + f4c * 2;
            *reinterpret_cast<uint2*>(&Xhi[so]) = xh;
            *reinterpret_cast<uint2*>(&Xlo[so]) = xl;
            *reinterpret_cast<uint2*>(&Whi[so]) = wh;
            *reinterpret_cast<uint2*>(&Wlo[so]) = wl;
        }
        __syncthreads();

#pragma unroll
        for (int ks = 0; ks < 2; ks++) {
            uint32_t ah[4], al[4];
            int ab = (w * 16 + lg) * GSTRIDE + ks * 8 + lt;
            ah[0] = Xhi[ab];      ah[1] = Xhi[ab + 8 * GSTRIDE];
            ah[2] = Xhi[ab + 4];  ah[3] = Xhi[ab + 8 * GSTRIDE + 4];
            al[0] = Xlo[ab];      al[1] = Xlo[ab + 8 * GSTRIDE];
            al[2] = Xlo[ab + 4];  al[3] = Xlo[ab + 8 * GSTRIDE + 4];
#pragma unroll
            for (int nf = 0; nf < 8; nf++) {
                int bb = (nf * 8 + lg) * GSTRIDE + ks * 8 + lt;
                uint32_t bh0 = Whi[bb], bh1 = Whi[bb + 4];
                uint32_t bl0 = Wlo[bb], bl1 = Wlo[bb + 4];
                mma_bf16(c[nf], ah, bh0, bh1);
                mma_bf16(c[nf], ah, bl0, bl1);
                mma_bf16(c[nf], al, bh0, bh1);
            }
        }
    }
}

// ---- fused QKV projection + bias + RoPE + transpose to [b,h,s,d] ----
// grid.x = 18 n-tiles: 0..13 -> Q head, 14..15 -> K kv-head, 16..17 -> V kv-head
__global__ __launch_bounds__(128) void gemm_qkv(const float* __restrict__ X,
                                                const float* __restrict__ Wq,
                                                const float* __restrict__ bq,
                                                const float* __restrict__ Wk,
                                                const float* __restrict__ bk,
                                                const float* __restrict__ Wv,
                                                const float* __restrict__ bv,
                                                const float2* __restrict__ rope,
                                                float* __restrict__ qo,
                                                float* __restrict__ ko,
                                                float* __restrict__ vo) {
    extern __shared__ uint32_t sm[];
    const int tid = threadIdx.x;
    const int w = tid >> 5;
    const int lane = tid & 31;
    const int lg = lane >> 2;
    const int lt = lane & 3;
    const int nt = blockIdx.x;
    const int m0 = blockIdx.y * 64;

    const float* Wsel;
    const float* bias;
    if (nt < 14)      { Wsel = Wq + (size_t)nt * 64 * HIDDEN;        bias = bq + nt * 64; }
    else if (nt < 16) { Wsel = Wk + (size_t)(nt - 14) * 64 * HIDDEN; bias = bk + (nt - 14) * 64; }
    else              { Wsel = Wv + (size_t)(nt - 16) * 64 * HIDDEN; bias = bv + (nt - 16) * 64; }

    float c[8][4];
    gemm_core(X, Wsel, HIDDEN, m0, c, sm, tid, w, lg, lt);

    // epilogue
#pragma unroll
    for (int rr = 0; rr < 2; rr++) {
        int row = m0 + w * 16 + lg + rr * 8;   // token index
        int b = row >> 11;                      // /S
        int s = row & (S - 1);
        if (nt < 16) {
            // rope path
            float* base = (nt < 14)
                ? qo + (((size_t)b * NH + nt) * S + s) * HD
                : ko + (((size_t)b * NKV + (nt - 14)) * S + s) * HD;
#pragma unroll
            for (int nf = 0; nf < 4; nf++) {
                int d0 = nf * 8 + 2 * lt;     // 0..30
                float2 t0 = rope[s * 32 + d0];
                float2 t1 = rope[s * 32 + d0 + 1];
                float x10 = c[nf][rr * 2 + 0] + bias[d0];
                float x11 = c[nf][rr * 2 + 1] + bias[d0 + 1];
                float x20 = c[nf + 4][rr * 2 + 0] + bias[d0 + 32];
                float x21 = c[nf + 4][rr * 2 + 1] + bias[d0 + 33];
                *reinterpret_cast<float2*>(base + d0) =
                    make_float2(x10 * t0.x - x20 * t0.y, x11 * t1.x - x21 * t1.y);
                *reinterpret_cast<float2*>(base + d0 + 32) =
                    make_float2(x20 * t0.x + x10 * t0.y, x21 * t1.x + x11 * t1.y);
            }
        } else {
            float* base = vo + (((size_t)b * NKV + (nt - 16)) * S + s) * HD;
#pragma unroll
            for (int nf = 0; nf < 8; nf++) {
                int d0 = nf * 8 + 2 * lt;
                *reinterpret_cast<float2*>(base + d0) =
                    make_float2(c[nf][rr * 2 + 0] + bias[d0], c[nf][rr * 2 + 1] + bias[d0 + 1]);
            }
        }
    }
}

// ---- output projection: plain C = X*Wo^T ----
__global__ __launch_bounds__(128) void gemm_out(const float* __restrict__ X,
                                                const float* __restrict__ Wo,
                                                float* __restrict__ C) {
    extern __shared__ uint32_t sm[];
    const int tid = threadIdx.x;
    const int w = tid >> 5;
    const int lane = tid & 31;
    const int lg = lane >> 2;
    const int lt = lane & 3;
    const int n0 = blockIdx.x * 64;
    const int m0 = blockIdx.y * 64;

    float c[8][4];
    gemm_core(X, Wo + (size_t)n0 * HIDDEN, HIDDEN, m0, c, sm, tid, w, lg, lt);

    const int row = m0 + w * 16 + lg;
#pragma unroll
    for (int nf = 0; nf < 8; nf++) {
        int col = n0 + nf * 8 + 2 * lt;
        *reinterpret_cast<float2*>(&C[(size_t)row * HIDDEN + col]) =
            make_float2(c[nf][0], c[nf][1]);
        *reinterpret_cast<float2*>(&C[(size_t)(row + 8) * HIDDEN + col]) =
            make_float2(c[nf][2], c[nf][3]);
    }
}

// ---------------- Flash attention: tf32 mma, 128 q-rows per CTA ----------------
#define KS_STRIDE 68
#define VS_STRIDE 72
#define PS_STRIDE 68
#define ATTN_SMEM ((64*KS_STRIDE + 64*VS_STRIDE + 128*PS_STRIDE) * 4)

__global__ __launch_bounds__(256) void attn_kernel(const float* __restrict__ Q,
                                                   const float* __restrict__ K,
                                                   const float* __restrict__ V,
                                                   float* __restrict__ O) {
    extern __shared__ uint32_t sm_u[];
    uint32_t* Ks = sm_u;                      // [64][68]
    uint32_t* Vs = Ks + 64 * KS_STRIDE;       // [64][72]
    uint32_t* Ps = Vs + 64 * VS_STRIDE;       // [128][68]

    const int qt = blockIdx.x;                // 128-row q tile
    const int h = blockIdx.y;
    const int b = blockIdx.z;
    const int kvh = h / NREP;
    const int tid = threadIdx.x;
    const int w = tid >> 5;                   // 8 warps
    const int lane = tid & 31;
    const int lg = lane >> 2;
    const int lt = lane & 3;

    const float* Qb = Q + (((size_t)b * NH + h) * S + (size_t)qt * 128) * HD;
    const float* Kb = K + (((size_t)b * NKV + kvh) * S) * HD;
    const float* Vb = V + (((size_t)b * NKV + kvh) * S) * HD;

    const float scale = 0.125f;   // 1/sqrt(64)
    uint32_t aq[8][4];
    {
        const int r0 = w * 16 + lg;
#pragma unroll
        for (int ks = 0; ks < 8; ks++) {
            int c0 = ks * 8 + lt;
            aq[ks][0] = f2tf32(scale * Qb[(size_t)r0 * HD + c0]);
            aq[ks][1] = f2tf32(scale * Qb[(size_t)(r0 + 8) * HD + c0]);
            aq[ks][2] = f2tf32(scale * Qb[(size_t)r0 * HD + c0 + 4]);
            aq[ks][3] = f2tf32(scale * Qb[(size_t)(r0 + 8) * HD + c0 + 4]);
        }
    }

    float o[8][4];
#pragma unroll
    for (int n = 0; n < 8; n++)
#pragma unroll
        for (int j = 0; j < 4; j++) o[n][j] = 0.f;
    float m0 = -1e30f, m1 = -1e30f, l0 = 0.f, l1 = 0.f;

    const int kt_end = 2 * qt + 1;            // inclusive
    for (int kt = 0; kt <= kt_end; kt++) {
        __syncthreads();
        // stage K,V tile (tf32), vectorized
#pragma unroll
        for (int i = tid; i < 64 * 16; i += 256) {
            int r = i >> 4, c4 = (i & 15) * 4;
            float4 kv = *reinterpret_cast<const float4*>(&Kb[((size_t)kt * 64 + r) * HD + c4]);
            float4 vv = *reinterpret_cast<const float4*>(&Vb[((size_t)kt * 64 + r) * HD + c4]);
            uint4 ku = make_uint4(f2tf32(kv.x), f2tf32(kv.y), f2tf32(kv.z), f2tf32(kv.w));
            uint4 vu = make_uint4(f2tf32(vv.x), f2tf32(vv.y), f2tf32(vv.z), f2tf32(vv.w));
            *reinterpret_cast<uint4*>(&Ks[r * KS_STRIDE + c4]) = ku;
            *reinterpret_cast<uint4*>(&Vs[r * VS_STRIDE + c4]) = vu;
        }
        __syncthreads();

        float c[8][4];
#pragma unroll
        for (int n = 0; n < 8; n++) {
#pragma unroll
            for (int j = 0; j < 4; j++) c[n][j] = 0.f;
#pragma unroll
            for (int ks = 0; ks < 8; ks++) {
                const uint32_t* krow = Ks + (n * 8 + lg) * KS_STRIDE + ks * 8 + lt;
                mma_tf32(c[n], aq[ks], krow[0], krow[4]);
            }
        }

        if (kt >= 2 * qt) {  // diagonal region
            const int row0 = qt * 128 + w * 16 + lg;
#pragma unroll
            for (int n = 0; n < 8; n++) {
                int col = kt * 64 + n * 8 + 2 * lt;
                if (col > row0)         c[n][0] = -1e30f;
                if (col + 1 > row0)     c[n][1] = -1e30f;
                if (col > row0 + 8)     c[n][2] = -1e30f;
                if (col + 1 > row0 + 8) c[n][3] = -1e30f;
            }
        }

        float mx0 = -1e30f, mx1 = -1e30f;
#pragma unroll
        for (int n = 0; n < 8; n++) {
            mx0 = fmaxf(mx0, fmaxf(c[n][0], c[n][1]));
            mx1 = fmaxf(mx1, fmaxf(c[n][2], c[n][3]));
        }
        mx0 = fmaxf(mx0, __shfl_xor_sync(0xffffffffu, mx0, 1));
        mx0 = fmaxf(mx0, __shfl_xor_sync(0xffffffffu, mx0, 2));
        mx1 = fmaxf(mx1, __shfl_xor_sync(0xffffffffu, mx1, 1));
        mx1 = fmaxf(mx1, __shfl_xor_sync(0xffffffffu, mx1, 2));

        float mn0 = fmaxf(m0, mx0);
        float mn1 = fmaxf(m1, mx1);
        float corr0 = __expf(m0 - mn0);
        float corr1 = __expf(m1 - mn1);

        float sum0 = 0.f, sum1 = 0.f;
        {
            const int r0 = w * 16 + lg;
            uint32_t* p0row = Ps + r0 * PS_STRIDE + 2 * lt;
            uint32_t* p1row = Ps + (r0 + 8) * PS_STRIDE + 2 * lt;
#pragma unroll
            for (int n = 0; n < 8; n++) {
                float p00 = __expf(c[n][0] - mn0);
                float p01 = __expf(c[n][1] - mn0);
                float p10 = __expf(c[n][2] - mn1);
                float p11 = __expf(c[n][3] - mn1);
                sum0 += p00 + p01;
                sum1 += p10 + p11;
                *reinterpret_cast<uint2*>(p0row + n * 8) = make_uint2(f2tf32(p00), f2tf32(p01));
                *reinterpret_cast<uint2*>(p1row + n * 8) = make_uint2(f2tf32(p10), f2tf32(p11));
            }
        }
        sum0 += __shfl_xor_sync(0xffffffffu, sum0, 1);
        sum0 += __shfl_xor_sync(0xffffffffu, sum0, 2);
        sum1 += __shfl_xor_sync(0xffffffffu, sum1, 1);
        sum1 += __shfl_xor_sync(0xffffffffu, sum1, 2);

        l0 = l0 * corr0 + sum0;
        l1 = l1 * corr1 + sum1;
        m0 = mn0;
        m1 = mn1;

#pragma unroll
        for (int n = 0; n < 8; n++) {
            o[n][0] *= corr0;
            o[n][1] *= corr0;
            o[n][2] *= corr1;
            o[n][3] *= corr1;
        }
        __syncwarp();

#pragma unroll
        for (int ks = 0; ks < 8; ks++) {
            uint32_t pa[4];
            const uint32_t* prow = Ps + (w * 16 + lg) * PS_STRIDE + ks * 8 + lt;
            pa[0] = prow[0];
            pa[1] = prow[8 * PS_STRIDE];
            pa[2] = prow[4];
            pa[3] = prow[8 * PS_STRIDE + 4];
#pragma unroll
            for (int n = 0; n < 8; n++) {
                const uint32_t* vrow = Vs + (ks * 8 + lt) * VS_STRIDE + n * 8 + lg;
                mma_tf32(o[n], pa, vrow[0], vrow[4 * VS_STRIDE]);
            }
        }
    }

    {
        float inv0 = 1.f / l0;
        float inv1 = 1.f / l1;
        const int r0 = qt * 128 + w * 16 + lg;
        float* out0 = O + ((size_t)b * S + r0) * HIDDEN + h * HD + 2 * lt;
        float* out1 = O + ((size_t)b * S + r0 + 8) * HIDDEN + h * HD + 2 * lt;
#pragma unroll
        for (int n = 0; n < 8; n++) {
            *reinterpret_cast<float2*>(out0 + n * 8) = make_float2(o[n][0] * inv0, o[n][1] * inv0);
            *reinterpret_cast<float2*>(out1 + n * 8) = make_float2(o[n][2] * inv1, o[n][3] * inv1);
        }
    }
}

// ---------------- launch ----------------
#define GEMM_SMEM (4 * 64 * GSTRIDE * 4)

extern "C" void kernel_launch(void* const* d_in, const int* in_sizes, int n_in,
                              void* d_out, int out_size) {
    const float* hs = (const float*)d_in[0];
    const float* Wq = (const float*)d_in[2];
    const float* bq = (const float*)d_in[3];
    const float* Wk = (const float*)d_in[4];
    const float* bk = (const float*)d_in[5];
    const float* Wv = (const float*)d_in[6];
    const float* bv = (const float*)d_in[7];
    const float* Wo = (const float*)d_in[8];
    float* out = (float*)d_out;

    float *q, *k, *v, *attn;
    float2* rope;
    cudaGetSymbolAddress((void**)&q, g_q);
    cudaGetSymbolAddress((void**)&k, g_k);
    cudaGetSymbolAddress((void**)&v, g_v);
    cudaGetSymbolAddress((void**)&attn, g_attn);
    cudaGetSymbolAddress((void**)&rope, g_rope);

    static bool attr_set = false;
    if (!attr_set) {
        cudaFuncSetAttribute(attn_kernel, cudaFuncAttributeMaxDynamicSharedMemorySize, ATTN_SMEM);
        attr_set = true;
    }

    // rope table
    build_rope<<<(S * 32) / 256, 256>>>(rope);

    // fused QKV projection + rope + transpose
    gemm_qkv<<<dim3(18, MTOK / 64), 128, GEMM_SMEM>>>(hs, Wq, bq, Wk, bk, Wv, bv, rope, q, k, v);

    // attention (tf32 tensor core), 128 q-rows per CTA
    attn_kernel<<<dim3(S / 128, NH, B), 256, ATTN_SMEM>>>(q, k, v, attn);

    // output projection
    gemm_out<<<dim3(HIDDEN / 64, MTOK / 64), 128, GEMM_SMEM>>>(attn, Wo, out);
}

// round 6
// speedup vs baseline: 3.1542x; 1.0362x over previous
#include <cuda_runtime.h>
#include <cuda_bf16.h>
#include <cstdint>

#define B 2
#define S 2048
#define HIDDEN 896
#define NH 14
#define NKV 2
#define HD 64
#define NREP 7
#define MTOK (B*S)          // 4096 tokens

// ---------------- scratch (device globals; no allocation allowed) ----------------
__device__ float g_q[B * NH * S * HD];         // [b,h,s,d]  (pre-scaled, tf32-rounded)
__device__ float g_k[B * NKV * S * HD];        // [b,kv,s,d] (tf32-rounded)
__device__ float g_v[B * NKV * S * HD];        // [b,kv,s,d] (tf32-rounded)
__device__ float g_attn[MTOK * HIDDEN];        // [b,s,h*d]
__device__ float2 g_rope[S * 32];              // cos,sin per (s, freq)

// Q pre-scale: 1/sqrt(64) * log2(e)  (softmax then uses exp2)
#define ASCALE 0.1803368801111204f

// ---------------- helpers ----------------
__device__ __forceinline__ uint32_t f2tf32(float x) {
    uint32_t r;
    asm("cvt.rna.tf32.f32 %0, %1;" : "=r"(r) : "f"(x));
    return r;
}

__device__ __forceinline__ void mma_tf32(float* d, const uint32_t* a, uint32_t b0, uint32_t b1) {
    asm volatile(
        "mma.sync.aligned.m16n8k8.row.col.f32.tf32.tf32.f32 "
        "{%0,%1,%2,%3}, {%4,%5,%6,%7}, {%8,%9}, {%0,%1,%2,%3};\n"
        : "+f"(d[0]), "+f"(d[1]), "+f"(d[2]), "+f"(d[3])
        : "r"(a[0]), "r"(a[1]), "r"(a[2]), "r"(a[3]), "r"(b0), "r"(b1));
}

__device__ __forceinline__ void mma_bf16(float* d, const uint32_t* a, uint32_t b0, uint32_t b1) {
    asm volatile(
        "mma.sync.aligned.m16n8k16.row.col.f32.bf16.bf16.f32 "
        "{%0,%1,%2,%3}, {%4,%5,%6,%7}, {%8,%9}, {%0,%1,%2,%3};\n"
        : "+f"(d[0]), "+f"(d[1]), "+f"(d[2]), "+f"(d[3])
        : "r"(a[0]), "r"(a[1]), "r"(a[2]), "r"(a[3]), "r"(b0), "r"(b1));
}

#define LDSM_X4(r0, r1, r2, r3, addr) \
    asm volatile("ldmatrix.sync.aligned.m8n8.x4.shared.b16 {%0,%1,%2,%3}, [%4];" \
                 : "=r"(r0), "=r"(r1), "=r"(r2), "=r"(r3) : "r"(addr))
#define LDSM_X2(r0, r1, addr) \
    asm volatile("ldmatrix.sync.aligned.m8n8.x2.shared.b16 {%0,%1}, [%2];" \
                 : "=r"(r0), "=r"(r1) : "r"(addr))

#define CP_ASYNC16(dst, src) \
    asm volatile("cp.async.ca.shared.global [%0], [%1], 16;" :: "r"(dst), "l"(src))

// pack two floats into bf16x2 hi word + bf16x2 lo (residual) word
__device__ __forceinline__ void split2(float x0, float x1, uint32_t& hi, uint32_t& lo) {
    asm("cvt.rn.bf16x2.f32 %0, %1, %2;" : "=r"(hi) : "f"(x1), "f"(x0));
    float h0 = __uint_as_float(hi << 16);
    float h1 = __uint_as_float(hi & 0xffff0000u);
    float r0 = x0 - h0;
    float r1 = x1 - h1;
    asm("cvt.rn.bf16x2.f32 %0, %1, %2;" : "=r"(lo) : "f"(r1), "f"(r0));
}

// ---------------- rope table ----------------
__global__ void build_rope(float2* tab) {
    int idx = blockIdx.x * blockDim.x + threadIdx.x;   // [0, S*32)
    int s = idx >> 5, i = idx & 31;
    const float LOG2_THETA_OVER_32 = 0.62286105580517513f;  // log2(1e6)/32
    float inv = exp2f(-(float)i * LOG2_THETA_OVER_32);
    float sn, cs;
    sincosf((float)s * inv, &sn, &cs);
    tab[idx] = make_float2(cs, sn);
}

// ---------------- GEMM core: bf16 hi/lo split, 64x64 tile, BK=32, 128 threads ----
#define GSTRIDE 20   // words per staged row (16 data + 4 pad); conflict-free

__device__ __forceinline__ void gemm_core(const float* __restrict__ X,
                                          const float* __restrict__ Wsel,
                                          int K, int m0, float c[8][4],
                                          uint32_t* sm, int tid, int w, int lane) {
    uint32_t* Xhi = sm;
    uint32_t* Xlo = sm + 64 * GSTRIDE;
    uint32_t* Whi = sm + 2 * 64 * GSTRIDE;
    uint32_t* Wlo = sm + 3 * 64 * GSTRIDE;

    const uint32_t sbase = (uint32_t)__cvta_generic_to_shared(sm);
    const uint32_t xhi_b = sbase;
    const uint32_t xlo_b = sbase + 64 * GSTRIDE * 4;
    const uint32_t whi_b = sbase + 2 * 64 * GSTRIDE * 4;
    const uint32_t wlo_b = sbase + 3 * 64 * GSTRIDE * 4;

    // ldmatrix address components
    const int arow = w * 16 + (lane & 15);
    const int acol = (lane >> 4) << 2;              // +4 words for lanes 16-31
    const int brow = lane & 7;
    const int bcol = ((lane >> 3) & 1) << 2;        // +4 words for lanes 8-15,24-31

#pragma unroll
    for (int n = 0; n < 8; n++)
#pragma unroll
        for (int j = 0; j < 4; j++) c[n][j] = 0.f;

    for (int k0 = 0; k0 < K; k0 += 32) {
        __syncthreads();
#pragma unroll
        for (int j = 0; j < 4; j++) {
            int idx = tid * 4 + j;
            int row = idx >> 3;         // 8 float4 per 32-wide row
            int f4c = idx & 7;
            float4 xv = *reinterpret_cast<const float4*>(&X[(size_t)(m0 + row) * K + k0 + f4c * 4]);
            float4 wv = *reinterpret_cast<const float4*>(&Wsel[(size_t)row * K + k0 + f4c * 4]);
            uint2 xh, xl, wh, wl;
            split2(xv.x, xv.y, xh.x, xl.x);
            split2(xv.z, xv.w, xh.y, xl.y);
            split2(wv.x, wv.y, wh.x, wl.x);
            split2(wv.z, wv.w, wh.y, wl.y);
            int so = row * GSTRIDE + f4c * 2;
            *reinterpret_cast<uint2*>(&Xhi[so]) = xh;
            *reinterpret_cast<uint2*>(&Xlo[so]) = xl;
            *reinterpret_cast<uint2*>(&Whi[so]) = wh;
            *reinterpret_cast<uint2*>(&Wlo[so]) = wl;
        }
        __syncthreads();

#pragma unroll
        for (int ks = 0; ks < 2; ks++) {
            uint32_t a_off = (uint32_t)((arow * GSTRIDE + ks * 8 + acol) * 4);
            uint32_t ah[4], al[4];
            LDSM_X4(ah[0], ah[1], ah[2], ah[3], xhi_b + a_off);
            LDSM_X4(al[0], al[1], al[2], al[3], xlo_b + a_off);
#pragma unroll
            for (int nf = 0; nf < 8; nf++) {
                uint32_t b_off = (uint32_t)(((nf * 8 + brow) * GSTRIDE + ks * 8 + bcol) * 4);
                uint32_t bh0, bh1, bl0, bl1;
                LDSM_X2(bh0, bh1, whi_b + b_off);
                LDSM_X2(bl0, bl1, wlo_b + b_off);
                mma_bf16(c[nf], ah, bh0, bh1);
                mma_bf16(c[nf], ah, bl0, bl1);
                mma_bf16(c[nf], al, bh0, bh1);
            }
        }
    }
}

// ---- fused QKV projection + bias + RoPE + transpose to [b,h,s,d] ----
// grid.x = 18 n-tiles: 0..13 -> Q head, 14..15 -> K kv-head, 16..17 -> V kv-head
// Q is pre-scaled by ASCALE; Q/K/V pre-rounded to tf32 (RNA) for the attention mma.
__global__ __launch_bounds__(128) void gemm_qkv(const float* __restrict__ X,
                                                const float* __restrict__ Wq,
                                                const float* __restrict__ bq,
                                                const float* __restrict__ Wk,
                                                const float* __restrict__ bk,
                                                const float* __restrict__ Wv,
                                                const float* __restrict__ bv,
                                                const float2* __restrict__ rope,
                                                float* __restrict__ qo,
                                                float* __restrict__ ko,
                                                float* __restrict__ vo) {
    extern __shared__ uint32_t sm[];
    const int tid = threadIdx.x;
    const int w = tid >> 5;
    const int lane = tid & 31;
    const int lg = lane >> 2;
    const int lt = lane & 3;
    const int nt = blockIdx.x;
    const int m0 = blockIdx.y * 64;

    const float* Wsel;
    const float* bias;
    if (nt < 14)      { Wsel = Wq + (size_t)nt * 64 * HIDDEN;        bias = bq + nt * 64; }
    else if (nt < 16) { Wsel = Wk + (size_t)(nt - 14) * 64 * HIDDEN; bias = bk + (nt - 14) * 64; }
    else              { Wsel = Wv + (size_t)(nt - 16) * 64 * HIDDEN; bias = bv + (nt - 16) * 64; }

    float c[8][4];
    gemm_core(X, Wsel, HIDDEN, m0, c, sm, tid, w, lane);

    // epilogue
#pragma unroll
    for (int rr = 0; rr < 2; rr++) {
        int row = m0 + w * 16 + lg + rr * 8;   // token index
        int b = row >> 11;                      // /S
        int s = row & (S - 1);
        if (nt < 16) {
            const bool isQ = (nt < 14);
            float* base = isQ
                ? qo + (((size_t)b * NH + nt) * S + s) * HD
                : ko + (((size_t)b * NKV + (nt - 14)) * S + s) * HD;
            const float sc = isQ ? ASCALE : 1.0f;
#pragma unroll
            for (int nf = 0; nf < 4; nf++) {
                int d0 = nf * 8 + 2 * lt;     // 0..30
                float2 t0 = rope[s * 32 + d0];
                float2 t1 = rope[s * 32 + d0 + 1];
                float x10 = c[nf][rr * 2 + 0] + bias[d0];
                float x11 = c[nf][rr * 2 + 1] + bias[d0 + 1];
                float x20 = c[nf + 4][rr * 2 + 0] + bias[d0 + 32];
                float x21 = c[nf + 4][rr * 2 + 1] + bias[d0 + 33];
                float y10 = (x10 * t0.x - x20 * t0.y) * sc;
                float y11 = (x11 * t1.x - x21 * t1.y) * sc;
                float y20 = (x20 * t0.x + x10 * t0.y) * sc;
                float y21 = (x21 * t1.x + x11 * t1.y) * sc;
                *reinterpret_cast<float2*>(base + d0) =
                    make_float2(__uint_as_float(f2tf32(y10)), __uint_as_float(f2tf32(y11)));
                *reinterpret_cast<float2*>(base + d0 + 32) =
                    make_float2(__uint_as_float(f2tf32(y20)), __uint_as_float(f2tf32(y21)));
            }
        } else {
            float* base = vo + (((size_t)b * NKV + (nt - 16)) * S + s) * HD;
#pragma unroll
            for (int nf = 0; nf < 8; nf++) {
                int d0 = nf * 8 + 2 * lt;
                *reinterpret_cast<float2*>(base + d0) = make_float2(
                    __uint_as_float(f2tf32(c[nf][rr * 2 + 0] + bias[d0])),
                    __uint_as_float(f2tf32(c[nf][rr * 2 + 1] + bias[d0 + 1])));
            }
        }
    }
}

// ---- output projection: plain C = X*Wo^T ----
__global__ __launch_bounds__(128) void gemm_out(const float* __restrict__ X,
                                                const float* __restrict__ Wo,
                                                float* __restrict__ C) {
    extern __shared__ uint32_t sm[];
    const int tid = threadIdx.x;
    const int w = tid >> 5;
    const int lane = tid & 31;
    const int lg = lane >> 2;
    const int lt = lane & 3;
    const int n0 = blockIdx.x * 64;
    const int m0 = blockIdx.y * 64;

    float c[8][4];
    gemm_core(X, Wo + (size_t)n0 * HIDDEN, HIDDEN, m0, c, sm, tid, w, lane);

    const int row = m0 + w * 16 + lg;
#pragma unroll
    for (int nf = 0; nf < 8; nf++) {
        int col = n0 + nf * 8 + 2 * lt;
        *reinterpret_cast<float2*>(&C[(size_t)row * HIDDEN + col]) =
            make_float2(c[nf][0], c[nf][1]);
        *reinterpret_cast<float2*>(&C[(size_t)(row + 8) * HIDDEN + col]) =
            make_float2(c[nf][2], c[nf][3]);
    }
}

// ---------------- Flash attention: tf32 mma, 128 q-rows per CTA ----------------
#define KS_STRIDE 68
#define VS_STRIDE 72
#define PS_STRIDE 68
#define ATTN_SMEM ((64*KS_STRIDE + 64*VS_STRIDE + 128*PS_STRIDE) * 4)

__global__ __launch_bounds__(256) void attn_kernel(const float* __restrict__ Q,
                                                   const float* __restrict__ K,
                                                   const float* __restrict__ V,
                                                   float* __restrict__ O) {
    extern __shared__ uint32_t sm_u[];
    uint32_t* Vs = sm_u + 64 * KS_STRIDE;     // [64][72]
    uint32_t* Ps = Vs + 64 * VS_STRIDE;       // [128][68]

    const uint32_t sbase = (uint32_t)__cvta_generic_to_shared(sm_u);
    const uint32_t ks_b = sbase;
    const uint32_t vs_b = sbase + 64 * KS_STRIDE * 4;
    const uint32_t ps_b = vs_b + 64 * VS_STRIDE * 4;

    const int qt = blockIdx.x;                // 128-row q tile
    const int h = blockIdx.y;
    const int b = blockIdx.z;
    const int kvh = h / NREP;
    const int tid = threadIdx.x;
    const int w = tid >> 5;                   // 8 warps
    const int lane = tid & 31;
    const int lg = lane >> 2;
    const int lt = lane & 3;

    const float* Qb = Q + (((size_t)b * NH + h) * S + (size_t)qt * 128) * HD;
    const float* Kb = K + (((size_t)b * NKV + kvh) * S) * HD;
    const float* Vb = V + (((size_t)b * NKV + kvh) * S) * HD;

    // Q fragments: raw bit loads (already scaled + tf32-rounded at projection)
    uint32_t aq[8][4];
    {
        const int r0 = w * 16 + lg;
#pragma unroll
        for (int ks = 0; ks < 8; ks++) {
            int c0 = ks * 8 + lt;
            aq[ks][0] = __float_as_uint(Qb[(size_t)r0 * HD + c0]);
            aq[ks][1] = __float_as_uint(Qb[(size_t)(r0 + 8) * HD + c0]);
            aq[ks][2] = __float_as_uint(Qb[(size_t)r0 * HD + c0 + 4]);
            aq[ks][3] = __float_as_uint(Qb[(size_t)(r0 + 8) * HD + c0 + 4]);
        }
    }

    // ldmatrix address components
    const int k_row = ((lane >> 4) << 3) + (lane & 7);   // 0..15
    const int k_col = ((lane >> 3) & 1) << 2;            // 0 or 4 words
    const int p_row = w * 16 + (lane & 15);
    const int p_col = (lane >> 4) << 2;

    float o[8][4];
#pragma unroll
    for (int n = 0; n < 8; n++)
#pragma unroll
        for (int j = 0; j < 4; j++) o[n][j] = 0.f;
    float m0 = -1e30f, m1 = -1e30f, l0 = 0.f, l1 = 0.f;

    const int kt_end = 2 * qt + 1;            // inclusive
    for (int kt = 0; kt <= kt_end; kt++) {
        __syncthreads();
        // stage K,V tiles via cp.async (pure copy, already tf32-rounded)
#pragma unroll
        for (int i = tid; i < 2048; i += 256) {
            int isV = i >> 10;
            int idx = i & 1023;
            int r = idx >> 4;
            int cw = (idx & 15) * 4;
            uint32_t dst = isV ? (vs_b + (uint32_t)((r * VS_STRIDE + cw) * 4))
                               : (ks_b + (uint32_t)((r * KS_STRIDE + cw) * 4));
            const float* src = (isV ? Vb : Kb) + ((size_t)kt * 64 + r) * HD + cw;
            CP_ASYNC16(dst, src);
        }
        asm volatile("cp.async.commit_group;\n cp.async.wait_group 0;\n" ::: "memory");
        __syncthreads();

        // ---- QK^T ----
        float c[8][4];
#pragma unroll
        for (int n = 0; n < 8; n++)
#pragma unroll
            for (int j = 0; j < 4; j++) c[n][j] = 0.f;
#pragma unroll
        for (int ks = 0; ks < 8; ks++) {
#pragma unroll
            for (int jp = 0; jp < 4; jp++) {
                uint32_t kb0, kb1, kb2, kb3;
                uint32_t addr = ks_b + (uint32_t)((((jp * 16) + k_row) * KS_STRIDE + ks * 8 + k_col) * 4);
                LDSM_X4(kb0, kb1, kb2, kb3, addr);
                mma_tf32(c[2 * jp], aq[ks], kb0, kb1);
                mma_tf32(c[2 * jp + 1], aq[ks], kb2, kb3);
            }
        }

        if (kt >= 2 * qt) {  // diagonal region
            const int row0 = qt * 128 + w * 16 + lg;
#pragma unroll
            for (int n = 0; n < 8; n++) {
                int col = kt * 64 + n * 8 + 2 * lt;
                if (col > row0)         c[n][0] = -1e30f;
                if (col + 1 > row0)     c[n][1] = -1e30f;
                if (col > row0 + 8)     c[n][2] = -1e30f;
                if (col + 1 > row0 + 8) c[n][3] = -1e30f;
            }
        }

        // ---- online softmax (log2 domain: Q pre-scaled by log2e/8) ----
        float mx0 = -1e30f, mx1 = -1e30f;
#pragma unroll
        for (int n = 0; n < 8; n++) {
            mx0 = fmaxf(mx0, fmaxf(c[n][0], c[n][1]));
            mx1 = fmaxf(mx1, fmaxf(c[n][2], c[n][3]));
        }
        mx0 = fmaxf(mx0, __shfl_xor_sync(0xffffffffu, mx0, 1));
        mx0 = fmaxf(mx0, __shfl_xor_sync(0xffffffffu, mx0, 2));
        mx1 = fmaxf(mx1, __shfl_xor_sync(0xffffffffu, mx1, 1));
        mx1 = fmaxf(mx1, __shfl_xor_sync(0xffffffffu, mx1, 2));

        float mn0 = fmaxf(m0, mx0);
        float mn1 = fmaxf(m1, mx1);
        float corr0 = exp2f(m0 - mn0);
        float corr1 = exp2f(m1 - mn1);

        float sum0 = 0.f, sum1 = 0.f;
        {
            const int r0 = w * 16 + lg;
            uint32_t* p0row = Ps + r0 * PS_STRIDE + 2 * lt;
            uint32_t* p1row = Ps + (r0 + 8) * PS_STRIDE + 2 * lt;
#pragma unroll
            for (int n = 0; n < 8; n++) {
                float p00 = exp2f(c[n][0] - mn0);
                float p01 = exp2f(c[n][1] - mn0);
                float p10 = exp2f(c[n][2] - mn1);
                float p11 = exp2f(c[n][3] - mn1);
                sum0 += p00 + p01;
                sum1 += p10 + p11;
                *reinterpret_cast<uint2*>(p0row + n * 8) = make_uint2(f2tf32(p00), f2tf32(p01));
                *reinterpret_cast<uint2*>(p1row + n * 8) = make_uint2(f2tf32(p10), f2tf32(p11));
            }
        }
        sum0 += __shfl_xor_sync(0xffffffffu, sum0, 1);
        sum0 += __shfl_xor_sync(0xffffffffu, sum0, 2);
        sum1 += __shfl_xor_sync(0xffffffffu, sum1, 1);
        sum1 += __shfl_xor_sync(0xffffffffu, sum1, 2);

        l0 = l0 * corr0 + sum0;
        l1 = l1 * corr1 + sum1;
        m0 = mn0;
        m1 = mn1;

#pragma unroll
        for (int n = 0; n < 8; n++) {
            o[n][0] *= corr0;
            o[n][1] *= corr0;
            o[n][2] *= corr1;
            o[n][3] *= corr1;
        }
        __syncwarp();

        // ---- P*V ----
#pragma unroll
        for (int ks = 0; ks < 8; ks++) {
            uint32_t pa[4];
            uint32_t paddr = ps_b + (uint32_t)((p_row * PS_STRIDE + ks * 8 + p_col) * 4);
            LDSM_X4(pa[0], pa[1], pa[2], pa[3], paddr);
#pragma unroll
            for (int n = 0; n < 8; n++) {
                const uint32_t* vrow = Vs + (ks * 8 + lt) * VS_STRIDE + n * 8 + lg;
                mma_tf32(o[n], pa, vrow[0], vrow[4 * VS_STRIDE]);
            }
        }
    }

    {
        float inv0 = 1.f / l0;
        float inv1 = 1.f / l1;
        const int r0 = qt * 128 + w * 16 + lg;
        float* out0 = O + ((size_t)b * S + r0) * HIDDEN + h * HD + 2 * lt;
        float* out1 = O + ((size_t)b * S + r0 + 8) * HIDDEN + h * HD + 2 * lt;
#pragma unroll
        for (int n = 0; n < 8; n++) {
            *reinterpret_cast<float2*>(out0 + n * 8) = make_float2(o[n][0] * inv0, o[n][1] * inv0);
            *reinterpret_cast<float2*>(out1 + n * 8) = make_float2(o[n][2] * inv1, o[n][3] * inv1);
        }
    }
}

// ---------------- launch ----------------
#define GEMM_SMEM (4 * 64 * GSTRIDE * 4)

extern "C" void kernel_launch(void* const* d_in, const int* in_sizes, int n_in,
                              void* d_out, int out_size) {
    const float* hs = (const float*)d_in[0];
    const float* Wq = (const float*)d_in[2];
    const float* bq = (const float*)d_in[3];
    const float* Wk = (const float*)d_in[4];
    const float* bk = (const float*)d_in[5];
    const float* Wv = (const float*)d_in[6];
    const float* bv = (const float*)d_in[7];
    const float* Wo = (const float*)d_in[8];
    float* out = (float*)d_out;

    float *q, *k, *v, *attn;
    float2* rope;
    cudaGetSymbolAddress((void**)&q, g_q);
    cudaGetSymbolAddress((void**)&k, g_k);
    cudaGetSymbolAddress((void**)&v, g_v);
    cudaGetSymbolAddress((void**)&attn, g_attn);
    cudaGetSymbolAddress((void**)&rope, g_rope);

    static bool attr_set = false;
    if (!attr_set) {
        cudaFuncSetAttribute(attn_kernel, cudaFuncAttributeMaxDynamicSharedMemorySize, ATTN_SMEM);
        attr_set = true;
    }

    // rope table
    build_rope<<<(S * 32) / 256, 256>>>(rope);

    // fused QKV projection + rope + transpose (+ tf32 pre-round, Q pre-scale)
    gemm_qkv<<<dim3(18, MTOK / 64), 128, GEMM_SMEM>>>(hs, Wq, bq, Wk, bk, Wv, bv, rope, q, k, v);

    // attention (tf32 tensor core), 128 q-rows per CTA
    attn_kernel<<<dim3(S / 128, NH, B), 256, ATTN_SMEM>>>(q, k, v, attn);

    // output projection
    gemm_out<<<dim3(HIDDEN / 64, MTOK / 64), 128, GEMM_SMEM>>>(attn, Wo, out);
}

// round 7
// speedup vs baseline: 4.1035x; 1.3009x over previous
#include <cuda_runtime.h>
#include <cuda_bf16.h>
#include <cstdint>

#define B 2
#define S 2048
#define HIDDEN 896
#define NH 14
#define NKV 2
#define HD 64
#define NREP 7
#define MTOK (B*S)          // 4096 tokens

// element counts (float4 units)
#define NX4  (MTOK*HIDDEN/4)        // 917504
#define NQ4  (HIDDEN*HIDDEN/4)      // 200704
#define NK4  (NKV*HD*HIDDEN/4)      // 28672
#define NV4  NK4
#define NO4  NQ4
#define TOT4 (NX4 + NQ4 + NK4 + NV4 + NO4)   // 1376256

// ---------------- scratch (device globals) ----------------
__device__ float g_q[B * NH * S * HD];         // [b,h,s,d]  (pre-scaled, tf32-rounded)
__device__ float g_k[B * NKV * S * HD];        // [b,kv,s,d] (tf32-rounded)
__device__ float g_vt[B * NKV * HD * S];       // [b,kv,d,s] TRANSPOSED (tf32-rounded)
__device__ float2 g_rope[S * 32];

// bf16 hi/lo pre-converted operands (uint2 = 4 bf16)
__device__ uint2 g_xhi[NX4],  g_xlo[NX4];      // hidden_states
__device__ uint2 g_wqhi[NQ4], g_wqlo[NQ4];
__device__ uint2 g_wkhi[NK4], g_wklo[NK4];
__device__ uint2 g_wvhi[NV4], g_wvlo[NV4];
__device__ uint2 g_wohi[NO4], g_wolo[NO4];
__device__ uint2 g_ahi[NX4],  g_alo[NX4];      // attention output

// Q pre-scale: 1/sqrt(64) * log2(e)
#define ASCALE 0.1803368801111204f

// ---------------- helpers ----------------
__device__ __forceinline__ uint32_t f2tf32(float x) {
    uint32_t r;
    asm("cvt.rna.tf32.f32 %0, %1;" : "=r"(r) : "f"(x));
    return r;
}

__device__ __forceinline__ void mma_tf32(float* d, const uint32_t* a, uint32_t b0, uint32_t b1) {
    asm volatile(
        "mma.sync.aligned.m16n8k8.row.col.f32.tf32.tf32.f32 "
        "{%0,%1,%2,%3}, {%4,%5,%6,%7}, {%8,%9}, {%0,%1,%2,%3};\n"
        : "+f"(d[0]), "+f"(d[1]), "+f"(d[2]), "+f"(d[3])
        : "r"(a[0]), "r"(a[1]), "r"(a[2]), "r"(a[3]), "r"(b0), "r"(b1));
}

__device__ __forceinline__ void mma_bf16(float* d, const uint32_t* a, uint32_t b0, uint32_t b1) {
    asm volatile(
        "mma.sync.aligned.m16n8k16.row.col.f32.bf16.bf16.f32 "
        "{%0,%1,%2,%3}, {%4,%5,%6,%7}, {%8,%9}, {%0,%1,%2,%3};\n"
        : "+f"(d[0]), "+f"(d[1]), "+f"(d[2]), "+f"(d[3])
        : "r"(a[0]), "r"(a[1]), "r"(a[2]), "r"(a[3]), "r"(b0), "r"(b1));
}

#define LDSM_X4(r0, r1, r2, r3, addr) \
    asm volatile("ldmatrix.sync.aligned.m8n8.x4.shared.b16 {%0,%1,%2,%3}, [%4];" \
                 : "=r"(r0), "=r"(r1), "=r"(r2), "=r"(r3) : "r"(addr))

#define CP_ASYNC16(dst, src) \
    asm volatile("cp.async.ca.shared.global [%0], [%1], 16;" :: "r"(dst), "l"(src))
#define CP_COMMIT() asm volatile("cp.async.commit_group;" ::: "memory")
#define CP_WAIT(n)  asm volatile("cp.async.wait_group %0;" :: "n"(n) : "memory")

// pack two floats into bf16x2 hi word + bf16x2 lo (residual) word
__device__ __forceinline__ void split2(float x0, float x1, uint32_t& hi, uint32_t& lo) {
    asm("cvt.rn.bf16x2.f32 %0, %1, %2;" : "=r"(hi) : "f"(x1), "f"(x0));
    float h0 = __uint_as_float(hi << 16);
    float h1 = __uint_as_float(hi & 0xffff0000u);
    float r0 = x0 - h0;
    float r1 = x1 - h1;
    asm("cvt.rn.bf16x2.f32 %0, %1, %2;" : "=r"(lo) : "f"(r1), "f"(r0));
}

// ---------------- conversion pass: fp32 -> bf16 hi/lo ----------------
__global__ void conv_split(const float4* __restrict__ x,
                           const float4* __restrict__ wq,
                           const float4* __restrict__ wk,
                           const float4* __restrict__ wv,
                           const float4* __restrict__ wo) {
    int i = blockIdx.x * blockDim.x + threadIdx.x;
    if (i >= TOT4) return;
    const float4* src;
    uint2 *hi, *lo;
    int off = i;
    if (off < NX4)                    { src = x;  hi = g_xhi;  lo = g_xlo; }
    else if ((off -= NX4) < NQ4)      { src = wq; hi = g_wqhi; lo = g_wqlo; }
    else if ((off -= NQ4) < NK4)      { src = wk; hi = g_wkhi; lo = g_wklo; }
    else if ((off -= NK4) < NV4)      { src = wv; hi = g_wvhi; lo = g_wvlo; }
    else { off -= NV4;                  src = wo; hi = g_wohi; lo = g_wolo; }
    float4 v = src[off];
    uint2 h, l;
    split2(v.x, v.y, h.x, l.x);
    split2(v.z, v.w, h.y, l.y);
    hi[off] = h;
    lo[off] = l;
}

// ---------------- rope table ----------------
__global__ void build_rope(float2* tab) {
    int idx = blockIdx.x * blockDim.x + threadIdx.x;   // [0, S*32)
    int s = idx >> 5, i = idx & 31;
    const float LOG2_THETA_OVER_32 = 0.62286105580517513f;  // log2(1e6)/32
    float inv = exp2f(-(float)i * LOG2_THETA_OVER_32);
    float sn, cs;
    sincosf((float)s * inv, &sn, &cs);
    tab[idx] = make_float2(cs, sn);
}

// ---------------- GEMM core: pre-split bf16, CTA 128x64, 128 thr, BK=32 ----------
// smem per buffer: XH[128][80B] XL WH[64][80B] WL  (pitch 80B = 40 bf16)
#define XH_OFF 0
#define XL_OFF 10240
#define WH_OFF 20480
#define WL_OFF 25600
#define GBUF   30720
#define GEMM_SMEM (2 * GBUF)
#define NKCH (HIDDEN / 32)     // 28

__device__ __forceinline__ void gemm3_core(const uint16_t* __restrict__ Ahi,
                                           const uint16_t* __restrict__ Alo,
                                           const uint16_t* __restrict__ Bhi,
                                           const uint16_t* __restrict__ Blo,
                                           int m0, float c[2][8][4],
                                           char* smem, int tid) {
    const int w = tid >> 5;
    const int lane = tid & 31;
    const uint32_t sb = (uint32_t)__cvta_generic_to_shared(smem);

    // ldmatrix lane address components
    const int arow = (lane & 7) + ((lane >> 3) & 1) * 8;
    const int acol = (lane >> 4) * 16;                    // bytes
    const int brow = (lane & 7) + ((lane >> 4) & 1) * 8;
    const int bcol = ((lane >> 3) & 1) * 16;              // bytes

#pragma unroll
    for (int mg = 0; mg < 2; mg++)
#pragma unroll
        for (int nf = 0; nf < 8; nf++)
#pragma unroll
            for (int j = 0; j < 4; j++) c[mg][nf][j] = 0.f;

    // stage chunk kc into buffer buf
    auto stage = [&](int kc, int buf) {
        int k0 = kc * 32;
        uint32_t base = sb + buf * GBUF;
#pragma unroll
        for (int t = 0; t < 4; t++) {
            int i = tid + t * 128;          // 0..511
            int row = i >> 2, c16 = i & 3;
            size_t so = ((size_t)(m0 + row) * HIDDEN + k0) * 2 + c16 * 16;
            uint32_t d = base + row * 80 + c16 * 16;
            CP_ASYNC16(d + XH_OFF, (const char*)Ahi + so);
            CP_ASYNC16(d + XL_OFF, (const char*)Alo + so);
        }
#pragma unroll
        for (int t = 0; t < 2; t++) {
            int i = tid + t * 128;          // 0..255
            int row = i >> 2, c16 = i & 3;
            size_t so = ((size_t)row * HIDDEN + k0) * 2 + c16 * 16;
            uint32_t d = base + row * 80 + c16 * 16;
            CP_ASYNC16(d + WH_OFF, (const char*)Bhi + so);
            CP_ASYNC16(d + WL_OFF, (const char*)Blo + so);
        }
    };

    stage(0, 0);
    CP_COMMIT();

    for (int kc = 0; kc < NKCH; kc++) {
        if (kc + 1 < NKCH) {
            stage(kc + 1, (kc + 1) & 1);
            CP_COMMIT();
            CP_WAIT(1);
        } else {
            CP_WAIT(0);
        }
        __syncthreads();

        uint32_t base = sb + (kc & 1) * GBUF;
#pragma unroll
        for (int ks = 0; ks < 2; ks++) {
            uint32_t ah[2][4], al[2][4];
#pragma unroll
            for (int mg = 0; mg < 2; mg++) {
                uint32_t aaddr = base + XH_OFF + (w * 32 + mg * 16 + arow) * 80 + acol + ks * 32;
                LDSM_X4(ah[mg][0], ah[mg][1], ah[mg][2], ah[mg][3], aaddr);
                LDSM_X4(al[mg][0], al[mg][1], al[mg][2], al[mg][3], aaddr + (XL_OFF - XH_OFF));
            }
#pragma unroll
            for (int np = 0; np < 4; np++) {
                uint32_t baddr = base + WH_OFF + (np * 16 + brow) * 80 + bcol + ks * 32;
                uint32_t bh0, bh1, bh2, bh3, bl0, bl1, bl2, bl3;
                LDSM_X4(bh0, bh1, bh2, bh3, baddr);
                LDSM_X4(bl0, bl1, bl2, bl3, baddr + (WL_OFF - WH_OFF));
#pragma unroll
                for (int mg = 0; mg < 2; mg++) {
                    mma_bf16(c[mg][2 * np],     ah[mg], bh0, bh1);
                    mma_bf16(c[mg][2 * np],     ah[mg], bl0, bl1);
                    mma_bf16(c[mg][2 * np],     al[mg], bh0, bh1);
                    mma_bf16(c[mg][2 * np + 1], ah[mg], bh2, bh3);
                    mma_bf16(c[mg][2 * np + 1], ah[mg], bl2, bl3);
                    mma_bf16(c[mg][2 * np + 1], al[mg], bh2, bh3);
                }
            }
        }
        __syncthreads();
    }
}

// ---- fused QKV projection + bias + RoPE + transpose ----
// grid (18, 32): nt 0..13 Q head, 14..15 K kv, 16..17 V kv (V written transposed [d][s])
__global__ __launch_bounds__(128) void gemm_qkv(const float* __restrict__ bq,
                                                const float* __restrict__ bk,
                                                const float* __restrict__ bv,
                                                const float2* __restrict__ rope,
                                                float* __restrict__ qo,
                                                float* __restrict__ ko,
                                                float* __restrict__ vt) {
    extern __shared__ char smem[];
    const int tid = threadIdx.x;
    const int w = tid >> 5;
    const int lane = tid & 31;
    const int lg = lane >> 2;
    const int lt = lane & 3;
    const int nt = blockIdx.x;
    const int m0 = blockIdx.y * 128;

    const uint16_t *Bhi, *Blo;
    const float* bias;
    if (nt < 14) {
        Bhi = (const uint16_t*)g_wqhi + (size_t)nt * 64 * HIDDEN;
        Blo = (const uint16_t*)g_wqlo + (size_t)nt * 64 * HIDDEN;
        bias = bq + nt * 64;
    } else if (nt < 16) {
        Bhi = (const uint16_t*)g_wkhi + (size_t)(nt - 14) * 64 * HIDDEN;
        Blo = (const uint16_t*)g_wklo + (size_t)(nt - 14) * 64 * HIDDEN;
        bias = bk + (nt - 14) * 64;
    } else {
        Bhi = (const uint16_t*)g_wvhi + (size_t)(nt - 16) * 64 * HIDDEN;
        Blo = (const uint16_t*)g_wvlo + (size_t)(nt - 16) * 64 * HIDDEN;
        bias = bv + (nt - 16) * 64;
    }

    float c[2][8][4];
    gemm3_core((const uint16_t*)g_xhi, (const uint16_t*)g_xlo, Bhi, Blo, m0, c, smem, tid);

#pragma unroll
    for (int mg = 0; mg < 2; mg++) {
#pragma unroll
        for (int rr = 0; rr < 2; rr++) {
            int row = m0 + w * 32 + mg * 16 + lg + rr * 8;   // token index
            int b = row >> 11;
            int s = row & (S - 1);
            if (nt < 16) {
                const bool isQ = (nt < 14);
                float* base = isQ
                    ? qo + (((size_t)b * NH + nt) * S + s) * HD
                    : ko + (((size_t)b * NKV + (nt - 14)) * S + s) * HD;
                const float sc = isQ ? ASCALE : 1.0f;
#pragma unroll
                for (int nf = 0; nf < 4; nf++) {
                    int d0 = nf * 8 + 2 * lt;
                    float2 t0 = rope[s * 32 + d0];
                    float2 t1 = rope[s * 32 + d0 + 1];
                    float x10 = c[mg][nf][rr * 2 + 0] + bias[d0];
                    float x11 = c[mg][nf][rr * 2 + 1] + bias[d0 + 1];
                    float x20 = c[mg][nf + 4][rr * 2 + 0] + bias[d0 + 32];
                    float x21 = c[mg][nf + 4][rr * 2 + 1] + bias[d0 + 33];
                    float y10 = (x10 * t0.x - x20 * t0.y) * sc;
                    float y11 = (x11 * t1.x - x21 * t1.y) * sc;
                    float y20 = (x20 * t0.x + x10 * t0.y) * sc;
                    float y21 = (x21 * t1.x + x11 * t1.y) * sc;
                    *reinterpret_cast<float2*>(base + d0) =
                        make_float2(__uint_as_float(f2tf32(y10)), __uint_as_float(f2tf32(y11)));
                    *reinterpret_cast<float2*>(base + d0 + 32) =
                        make_float2(__uint_as_float(f2tf32(y20)), __uint_as_float(f2tf32(y21)));
                }
            } else {
                // V transposed: [b][kv][d][s]
                float* base = vt + ((size_t)(b * NKV + (nt - 16)) * HD) * S + s;
#pragma unroll
                for (int nf = 0; nf < 8; nf++) {
                    int d0 = nf * 8 + 2 * lt;
                    base[(size_t)d0 * S] =
                        __uint_as_float(f2tf32(c[mg][nf][rr * 2 + 0] + bias[d0]));
                    base[(size_t)(d0 + 1) * S] =
                        __uint_as_float(f2tf32(c[mg][nf][rr * 2 + 1] + bias[d0 + 1]));
                }
            }
        }
    }
}

// ---- output projection: d_out = attn * Wo^T ----
__global__ __launch_bounds__(128) void gemm_out(float* __restrict__ C) {
    extern __shared__ char smem[];
    const int tid = threadIdx.x;
    const int w = tid >> 5;
    const int lane = tid & 31;
    const int lg = lane >> 2;
    const int lt = lane & 3;
    const int n0 = blockIdx.x * 64;
    const int m0 = blockIdx.y * 128;

    float c[2][8][4];
    gemm3_core((const uint16_t*)g_ahi, (const uint16_t*)g_alo,
               (const uint16_t*)g_wohi + (size_t)n0 * HIDDEN,
               (const uint16_t*)g_wolo + (size_t)n0 * HIDDEN,
               m0, c, smem, tid);

#pragma unroll
    for (int mg = 0; mg < 2; mg++) {
        const int row = m0 + w * 32 + mg * 16 + lg;
#pragma unroll
        for (int nf = 0; nf < 8; nf++) {
            int col = n0 + nf * 8 + 2 * lt;
            *reinterpret_cast<float2*>(&C[(size_t)row * HIDDEN + col]) =
                make_float2(c[mg][nf][0], c[mg][nf][1]);
            *reinterpret_cast<float2*>(&C[(size_t)(row + 8) * HIDDEN + col]) =
                make_float2(c[mg][nf][2], c[mg][nf][3]);
        }
    }
}

// ---------------- Flash attention: tf32 mma, 128 q/CTA, double-buffered ----------
#define AST 68   // word stride for K / Vt / P tiles
#define ATILE (64 * AST)          // words per K or Vt buffer
#define ATTN_SMEM ((4 * ATILE + 128 * AST) * 4)

__global__ __launch_bounds__(256) void attn_kernel(const float* __restrict__ Q,
                                                   const float* __restrict__ K,
                                                   const float* __restrict__ V,   // transposed [d][s]
                                                   uint32_t* __restrict__ Ohi,
                                                   uint32_t* __restrict__ Olo) {
    extern __shared__ uint32_t sm_u[];
    uint32_t* Ps = sm_u + 4 * ATILE;          // [128][68]

    const uint32_t sbase = (uint32_t)__cvta_generic_to_shared(sm_u);
    const uint32_t ps_b = sbase + 4 * ATILE * 4;

    const int qt = blockIdx.x;
    const int h = blockIdx.y;
    const int b = blockIdx.z;
    const int kvh = h / NREP;
    const int tid = threadIdx.x;
    const int w = tid >> 5;
    const int lane = tid & 31;
    const int lg = lane >> 2;
    const int lt = lane & 3;

    const float* Qb = Q + (((size_t)b * NH + h) * S + (size_t)qt * 128) * HD;
    const float* Kb = K + (((size_t)b * NKV + kvh) * S) * HD;
    const float* Vtb = V + ((size_t)(b * NKV + kvh) * HD) * S;

    // Q fragments (pre-scaled, tf32-rounded at projection)
    uint32_t aq[8][4];
    {
        const int r0 = w * 16 + lg;
#pragma unroll
        for (int ks = 0; ks < 8; ks++) {
            int c0 = ks * 8 + lt;
            aq[ks][0] = __float_as_uint(Qb[(size_t)r0 * HD + c0]);
            aq[ks][1] = __float_as_uint(Qb[(size_t)(r0 + 8) * HD + c0]);
            aq[ks][2] = __float_as_uint(Qb[(size_t)r0 * HD + c0 + 4]);
            aq[ks][3] = __float_as_uint(Qb[(size_t)(r0 + 8) * HD + c0 + 4]);
        }
    }

    // ldmatrix lane address components (shared by K / Vt / P patterns)
    const int k_row = ((lane >> 4) << 3) + (lane & 7);
    const int k_col = ((lane >> 3) & 1) << 2;            // words
    const int p_row = w * 16 + (lane & 15);
    const int p_col = (lane >> 4) << 2;

    float o[8][4];
#pragma unroll
    for (int n = 0; n < 8; n++)
#pragma unroll
        for (int j = 0; j < 4; j++) o[n][j] = 0.f;
    float m0 = -1e30f, m1 = -1e30f, l0 = 0.f, l1 = 0.f;

    const int kt_end = 2 * qt + 1;

    auto stage = [&](int kt, int buf) {
        uint32_t kb = sbase + buf * ATILE * 4;
        uint32_t vb = sbase + (2 + buf) * ATILE * 4;
#pragma unroll
        for (int i = tid; i < 2048; i += 256) {
            int isV = i >> 10;
            int idx = i & 1023;
            int r = idx >> 4;
            int cw = (idx & 15) * 4;
            if (isV) {
                CP_ASYNC16(vb + (uint32_t)((r * AST + cw) * 4),
                           Vtb + (size_t)r * S + (size_t)kt * 64 + cw);
            } else {
                CP_ASYNC16(kb + (uint32_t)((r * AST + cw) * 4),
                           Kb + ((size_t)kt * 64 + r) * HD + cw);
            }
        }
    };

    stage(0, 0);
    CP_COMMIT();

    for (int kt = 0; kt <= kt_end; kt++) {
        const int cur = kt & 1;
        if (kt < kt_end) {
            stage(kt + 1, cur ^ 1);
            CP_COMMIT();
            CP_WAIT(1);
        } else {
            CP_WAIT(0);
        }
        __syncthreads();

        const uint32_t kb = sbase + cur * ATILE * 4;
        const uint32_t vb = sbase + (2 + cur) * ATILE * 4;

        // ---- QK^T ----
        float c[8][4];
#pragma unroll
        for (int n = 0; n < 8; n++)
#pragma unroll
            for (int j = 0; j < 4; j++) c[n][j] = 0.f;
#pragma unroll
        for (int ks = 0; ks < 8; ks++) {
#pragma unroll
            for (int jp = 0; jp < 4; jp++) {
                uint32_t kb0, kb1, kb2, kb3;
                uint32_t addr = kb + (uint32_t)(((jp * 16 + k_row) * AST + ks * 8 + k_col) * 4);
                LDSM_X4(kb0, kb1, kb2, kb3, addr);
                mma_tf32(c[2 * jp], aq[ks], kb0, kb1);
                mma_tf32(c[2 * jp + 1], aq[ks], kb2, kb3);
            }
        }

        if (kt >= 2 * qt) {
            const int row0 = qt * 128 + w * 16 + lg;
#pragma unroll
            for (int n = 0; n < 8; n++) {
                int col = kt * 64 + n * 8 + 2 * lt;
                if (col > row0)         c[n][0] = -1e30f;
                if (col + 1 > row0)     c[n][1] = -1e30f;
                if (col > row0 + 8)     c[n][2] = -1e30f;
                if (col + 1 > row0 + 8) c[n][3] = -1e30f;
            }
        }

        // ---- online softmax (log2 domain) ----
        float mx0 = -1e30f, mx1 = -1e30f;
#pragma unroll
        for (int n = 0; n < 8; n++) {
            mx0 = fmaxf(mx0, fmaxf(c[n][0], c[n][1]));
            mx1 = fmaxf(mx1, fmaxf(c[n][2], c[n][3]));
        }
        mx0 = fmaxf(mx0, __shfl_xor_sync(0xffffffffu, mx0, 1));
        mx0 = fmaxf(mx0, __shfl_xor_sync(0xffffffffu, mx0, 2));
        mx1 = fmaxf(mx1, __shfl_xor_sync(0xffffffffu, mx1, 1));
        mx1 = fmaxf(mx1, __shfl_xor_sync(0xffffffffu, mx1, 2));

        float mn0 = fmaxf(m0, mx0);
        float mn1 = fmaxf(m1, mx1);
        float corr0 = exp2f(m0 - mn0);
        float corr1 = exp2f(m1 - mn1);

        float sum0 = 0.f, sum1 = 0.f;
        {
            const int r0 = w * 16 + lg;
            uint32_t* p0row = Ps + r0 * AST + 2 * lt;
            uint32_t* p1row = Ps + (r0 + 8) * AST + 2 * lt;
#pragma unroll
            for (int n = 0; n < 8; n++) {
                float p00 = exp2f(c[n][0] - mn0);
                float p01 = exp2f(c[n][1] - mn0);
                float p10 = exp2f(c[n][2] - mn1);
                float p11 = exp2f(c[n][3] - mn1);
                sum0 += p00 + p01;
                sum1 += p10 + p11;
                *reinterpret_cast<uint2*>(p0row + n * 8) = make_uint2(f2tf32(p00), f2tf32(p01));
                *reinterpret_cast<uint2*>(p1row + n * 8) = make_uint2(f2tf32(p10), f2tf32(p11));
            }
        }
        sum0 += __shfl_xor_sync(0xffffffffu, sum0, 1);
        sum0 += __shfl_xor_sync(0xffffffffu, sum0, 2);
        sum1 += __shfl_xor_sync(0xffffffffu, sum1, 1);
        sum1 += __shfl_xor_sync(0xffffffffu, sum1, 2);

        l0 = l0 * corr0 + sum0;
        l1 = l1 * corr1 + sum1;
        m0 = mn0;
        m1 = mn1;

#pragma unroll
        for (int n = 0; n < 8; n++) {
            o[n][0] *= corr0;
            o[n][1] *= corr0;
            o[n][2] *= corr1;
            o[n][3] *= corr1;
        }
        __syncwarp();

        // ---- P*V (Vt staged [d][key]; same ldsm pattern as K) ----
#pragma unroll
        for (int ks = 0; ks < 8; ks++) {
            uint32_t pa[4];
            uint32_t paddr = ps_b + (uint32_t)((p_row * AST + ks * 8 + p_col) * 4);
            LDSM_X4(pa[0], pa[1], pa[2], pa[3], paddr);
#pragma unroll
            for (int jp = 0; jp < 4; jp++) {
                uint32_t v0, v1, v2, v3;
                uint32_t addr = vb + (uint32_t)(((jp * 16 + k_row) * AST + ks * 8 + k_col) * 4);
                LDSM_X4(v0, v1, v2, v3, addr);
                mma_tf32(o[2 * jp], pa, v0, v1);
                mma_tf32(o[2 * jp + 1], pa, v2, v3);
            }
        }
        __syncthreads();
    }

    // ---- write normalized output as bf16 hi/lo ----
    {
        float inv0 = 1.f / l0;
        float inv1 = 1.f / l1;
        const int r0 = qt * 128 + w * 16 + lg;
        size_t base0 = ((size_t)b * S + r0) * HIDDEN + h * HD + 2 * lt;
        size_t base1 = ((size_t)b * S + r0 + 8) * HIDDEN + h * HD + 2 * lt;
#pragma unroll
        for (int n = 0; n < 8; n++) {
            uint32_t hi, lo;
            split2(o[n][0] * inv0, o[n][1] * inv0, hi, lo);
            Ohi[(base0 + n * 8) >> 1] = hi;
            Olo[(base0 + n * 8) >> 1] = lo;
            split2(o[n][2] * inv1, o[n][3] * inv1, hi, lo);
            Ohi[(base1 + n * 8) >> 1] = hi;
            Olo[(base1 + n * 8) >> 1] = lo;
        }
    }
}

// ---------------- launch ----------------
extern "C" void kernel_launch(void* const* d_in, const int* in_sizes, int n_in,
                              void* d_out, int out_size) {
    const float* hs = (const float*)d_in[0];
    const float* Wq = (const float*)d_in[2];
    const float* bq = (const float*)d_in[3];
    const float* Wk = (const float*)d_in[4];
    const float* bk = (const float*)d_in[5];
    const float* Wv = (const float*)d_in[6];
    const float* bv = (const float*)d_in[7];
    const float* Wo = (const float*)d_in[8];
    float* out = (float*)d_out;

    float *q, *k, *vt;
    float2* rope;
    uint2 *ahi, *alo;
    cudaGetSymbolAddress((void**)&q, g_q);
    cudaGetSymbolAddress((void**)&k, g_k);
    cudaGetSymbolAddress((void**)&vt, g_vt);
    cudaGetSymbolAddress((void**)&rope, g_rope);
    cudaGetSymbolAddress((void**)&ahi, g_ahi);
    cudaGetSymbolAddress((void**)&alo, g_alo);

    static bool attr_set = false;
    if (!attr_set) {
        cudaFuncSetAttribute(attn_kernel, cudaFuncAttributeMaxDynamicSharedMemorySize, ATTN_SMEM);
        cudaFuncSetAttribute(gemm_qkv, cudaFuncAttributeMaxDynamicSharedMemorySize, GEMM_SMEM);
        cudaFuncSetAttribute(gemm_out, cudaFuncAttributeMaxDynamicSharedMemorySize, GEMM_SMEM);
        attr_set = true;
    }

    build_rope<<<(S * 32) / 256, 256>>>(rope);
    conv_split<<<(TOT4 + 255) / 256, 256>>>((const float4*)hs, (const float4*)Wq,
                                            (const float4*)Wk, (const float4*)Wv,
                                            (const float4*)Wo);

    gemm_qkv<<<dim3(18, MTOK / 128), 128, GEMM_SMEM>>>(bq, bk, bv, rope, q, k, vt);

    attn_kernel<<<dim3(S / 128, NH, B), 256, ATTN_SMEM>>>(q, k, vt,
                                                          (uint32_t*)ahi, (uint32_t*)alo);

    gemm_out<<<dim3(HIDDEN / 64, MTOK / 128), 128, GEMM_SMEM>>>(out);
}

// round 8
// speedup vs baseline: 4.4056x; 1.0736x over previous
#include <cuda_runtime.h>
#include <cuda_bf16.h>
#include <cstdint>

#define B 2
#define S 2048
#define HIDDEN 896
#define NH 14
#define NKV 2
#define HD 64
#define NREP 7
#define MTOK (B*S)          // 4096 tokens

// element counts (float4 units)
#define NX4  (MTOK*HIDDEN/4)        // 917504
#define NQ4  (HIDDEN*HIDDEN/4)      // 200704
#define NK4  (NKV*HD*HIDDEN/4)      // 28672
#define NV4  NK4
#define NO4  NQ4
#define TOT4 (NX4 + NQ4 + NK4 + NV4 + NO4)   // 1376256

// ---------------- scratch (device globals) ----------------
__device__ float g_q[B * NH * S * HD];         // [b,h,s,d]  (pre-scaled, tf32-rounded)
__device__ float g_k[B * NKV * S * HD];        // [b,kv,s,d] (tf32-rounded)
__device__ float g_vt[B * NKV * HD * S];       // [b,kv,d,s] TRANSPOSED (tf32-rounded)
__device__ float2 g_rope[S * 32];

// bf16 hi/lo pre-converted operands (uint2 = 4 bf16)
__device__ uint2 g_xhi[NX4],  g_xlo[NX4];      // hidden_states
__device__ uint2 g_wqhi[NQ4], g_wqlo[NQ4];
__device__ uint2 g_wkhi[NK4], g_wklo[NK4];
__device__ uint2 g_wvhi[NV4], g_wvlo[NV4];
__device__ uint2 g_wohi[NO4], g_wolo[NO4];
__device__ uint2 g_ahi[NX4],  g_alo[NX4];      // attention output

// Q pre-scale: 1/sqrt(64) * log2(e)
#define ASCALE 0.1803368801111204f

// ---------------- helpers ----------------
__device__ __forceinline__ uint32_t f2tf32(float x) {
    uint32_t r;
    asm("cvt.rna.tf32.f32 %0, %1;" : "=r"(r) : "f"(x));
    return r;
}

__device__ __forceinline__ void mma_tf32(float* d, const uint32_t* a, uint32_t b0, uint32_t b1) {
    asm volatile(
        "mma.sync.aligned.m16n8k8.row.col.f32.tf32.tf32.f32 "
        "{%0,%1,%2,%3}, {%4,%5,%6,%7}, {%8,%9}, {%0,%1,%2,%3};\n"
        : "+f"(d[0]), "+f"(d[1]), "+f"(d[2]), "+f"(d[3])
        : "r"(a[0]), "r"(a[1]), "r"(a[2]), "r"(a[3]), "r"(b0), "r"(b1));
}

__device__ __forceinline__ void mma_bf16(float* d, const uint32_t* a, uint32_t b0, uint32_t b1) {
    asm volatile(
        "mma.sync.aligned.m16n8k16.row.col.f32.bf16.bf16.f32 "
        "{%0,%1,%2,%3}, {%4,%5,%6,%7}, {%8,%9}, {%0,%1,%2,%3};\n"
        : "+f"(d[0]), "+f"(d[1]), "+f"(d[2]), "+f"(d[3])
        : "r"(a[0]), "r"(a[1]), "r"(a[2]), "r"(a[3]), "r"(b0), "r"(b1));
}

#define LDSM_X4(r0, r1, r2, r3, addr) \
    asm volatile("ldmatrix.sync.aligned.m8n8.x4.shared.b16 {%0,%1,%2,%3}, [%4];" \
                 : "=r"(r0), "=r"(r1), "=r"(r2), "=r"(r3) : "r"(addr))

#define CP_ASYNC16(dst, src) \
    asm volatile("cp.async.ca.shared.global [%0], [%1], 16;" :: "r"(dst), "l"(src))
#define CP_COMMIT() asm volatile("cp.async.commit_group;" ::: "memory")
#define CP_WAIT(n)  asm volatile("cp.async.wait_group %0;" :: "n"(n) : "memory")

// pack two floats into bf16x2 hi word + bf16x2 lo (residual) word
__device__ __forceinline__ void split2(float x0, float x1, uint32_t& hi, uint32_t& lo) {
    asm("cvt.rn.bf16x2.f32 %0, %1, %2;" : "=r"(hi) : "f"(x1), "f"(x0));
    float h0 = __uint_as_float(hi << 16);
    float h1 = __uint_as_float(hi & 0xffff0000u);
    float r0 = x0 - h0;
    float r1 = x1 - h1;
    asm("cvt.rn.bf16x2.f32 %0, %1, %2;" : "=r"(lo) : "f"(r1), "f"(r0));
}

// ---------------- conversion pass: fp32 -> bf16 hi/lo ----------------
__global__ void conv_split(const float4* __restrict__ x,
                           const float4* __restrict__ wq,
                           const float4* __restrict__ wk,
                           const float4* __restrict__ wv,
                           const float4* __restrict__ wo) {
    int i = blockIdx.x * blockDim.x + threadIdx.x;
    if (i >= TOT4) return;
    const float4* src;
    uint2 *hi, *lo;
    int off = i;
    if (off < NX4)                    { src = x;  hi = g_xhi;  lo = g_xlo; }
    else if ((off -= NX4) < NQ4)      { src = wq; hi = g_wqhi; lo = g_wqlo; }
    else if ((off -= NQ4) < NK4)      { src = wk; hi = g_wkhi; lo = g_wklo; }
    else if ((off -= NK4) < NV4)      { src = wv; hi = g_wvhi; lo = g_wvlo; }
    else { off -= NV4;                  src = wo; hi = g_wohi; lo = g_wolo; }
    float4 v = src[off];
    uint2 h, l;
    split2(v.x, v.y, h.x, l.x);
    split2(v.z, v.w, h.y, l.y);
    hi[off] = h;
    lo[off] = l;
}

// ---------------- rope table ----------------
__global__ void build_rope(float2* tab) {
    int idx = blockIdx.x * blockDim.x + threadIdx.x;   // [0, S*32)
    int s = idx >> 5, i = idx & 31;
    const float LOG2_THETA_OVER_32 = 0.62286105580517513f;  // log2(1e6)/32
    float inv = exp2f(-(float)i * LOG2_THETA_OVER_32);
    float sn, cs;
    sincosf((float)s * inv, &sn, &cs);
    tab[idx] = make_float2(cs, sn);
}

// ---------------- GEMM core: pre-split bf16, CTA 128x64, 128 thr, BK=32 ----------
#define XH_OFF 0
#define XL_OFF 10240
#define WH_OFF 20480
#define WL_OFF 25600
#define GBUF   30720
#define GEMM_SMEM (2 * GBUF)
#define NKCH (HIDDEN / 32)     // 28

__device__ __forceinline__ void gemm3_core(const uint16_t* __restrict__ Ahi,
                                           const uint16_t* __restrict__ Alo,
                                           const uint16_t* __restrict__ Bhi,
                                           const uint16_t* __restrict__ Blo,
                                           int m0, float c[2][8][4],
                                           char* smem, int tid) {
    const int w = tid >> 5;
    const int lane = tid & 31;
    const uint32_t sb = (uint32_t)__cvta_generic_to_shared(smem);

    const int arow = (lane & 7) + ((lane >> 3) & 1) * 8;
    const int acol = (lane >> 4) * 16;                    // bytes
    const int brow = (lane & 7) + ((lane >> 4) & 1) * 8;
    const int bcol = ((lane >> 3) & 1) * 16;              // bytes

#pragma unroll
    for (int mg = 0; mg < 2; mg++)
#pragma unroll
        for (int nf = 0; nf < 8; nf++)
#pragma unroll
            for (int j = 0; j < 4; j++) c[mg][nf][j] = 0.f;

    auto stage = [&](int kc, int buf) {
        int k0 = kc * 32;
        uint32_t base = sb + buf * GBUF;
#pragma unroll
        for (int t = 0; t < 4; t++) {
            int i = tid + t * 128;
            int row = i >> 2, c16 = i & 3;
            size_t so = ((size_t)(m0 + row) * HIDDEN + k0) * 2 + c16 * 16;
            uint32_t d = base + row * 80 + c16 * 16;
            CP_ASYNC16(d + XH_OFF, (const char*)Ahi + so);
            CP_ASYNC16(d + XL_OFF, (const char*)Alo + so);
        }
#pragma unroll
        for (int t = 0; t < 2; t++) {
            int i = tid + t * 128;
            int row = i >> 2, c16 = i & 3;
            size_t so = ((size_t)row * HIDDEN + k0) * 2 + c16 * 16;
            uint32_t d = base + row * 80 + c16 * 16;
            CP_ASYNC16(d + WH_OFF, (const char*)Bhi + so);
            CP_ASYNC16(d + WL_OFF, (const char*)Blo + so);
        }
    };

    stage(0, 0);
    CP_COMMIT();

    for (int kc = 0; kc < NKCH; kc++) {
        if (kc + 1 < NKCH) {
            stage(kc + 1, (kc + 1) & 1);
            CP_COMMIT();
            CP_WAIT(1);
        } else {
            CP_WAIT(0);
        }
        __syncthreads();

        uint32_t base = sb + (kc & 1) * GBUF;
#pragma unroll
        for (int ks = 0; ks < 2; ks++) {
            uint32_t ah[2][4], al[2][4];
#pragma unroll
            for (int mg = 0; mg < 2; mg++) {
                uint32_t aaddr = base + XH_OFF + (w * 32 + mg * 16 + arow) * 80 + acol + ks * 32;
                LDSM_X4(ah[mg][0], ah[mg][1], ah[mg][2], ah[mg][3], aaddr);
                LDSM_X4(al[mg][0], al[mg][1], al[mg][2], al[mg][3], aaddr + (XL_OFF - XH_OFF));
            }
#pragma unroll
            for (int np = 0; np < 4; np++) {
                uint32_t baddr = base + WH_OFF + (np * 16 + brow) * 80 + bcol + ks * 32;
                uint32_t bh0, bh1, bh2, bh3, bl0, bl1, bl2, bl3;
                LDSM_X4(bh0, bh1, bh2, bh3, baddr);
                LDSM_X4(bl0, bl1, bl2, bl3, baddr + (WL_OFF - WH_OFF));
#pragma unroll
                for (int mg = 0; mg < 2; mg++) {
                    mma_bf16(c[mg][2 * np],     ah[mg], bh0, bh1);
                    mma_bf16(c[mg][2 * np],     ah[mg], bl0, bl1);
                    mma_bf16(c[mg][2 * np],     al[mg], bh0, bh1);
                    mma_bf16(c[mg][2 * np + 1], ah[mg], bh2, bh3);
                    mma_bf16(c[mg][2 * np + 1], ah[mg], bl2, bl3);
                    mma_bf16(c[mg][2 * np + 1], al[mg], bh2, bh3);
                }
            }
        }
        __syncthreads();
    }
}

// ---- fused QKV projection + bias + RoPE + transpose ----
__global__ __launch_bounds__(128) void gemm_qkv(const float* __restrict__ bq,
                                                const float* __restrict__ bk,
                                                const float* __restrict__ bv,
                                                const float2* __restrict__ rope,
                                                float* __restrict__ qo,
                                                float* __restrict__ ko,
                                                float* __restrict__ vt) {
    extern __shared__ char smem[];
    const int tid = threadIdx.x;
    const int w = tid >> 5;
    const int lane = tid & 31;
    const int lg = lane >> 2;
    const int lt = lane & 3;
    const int nt = blockIdx.x;
    const int m0 = blockIdx.y * 128;

    const uint16_t *Bhi, *Blo;
    const float* bias;
    if (nt < 14) {
        Bhi = (const uint16_t*)g_wqhi + (size_t)nt * 64 * HIDDEN;
        Blo = (const uint16_t*)g_wqlo + (size_t)nt * 64 * HIDDEN;
        bias = bq + nt * 64;
    } else if (nt < 16) {
        Bhi = (const uint16_t*)g_wkhi + (size_t)(nt - 14) * 64 * HIDDEN;
        Blo = (const uint16_t*)g_wklo + (size_t)(nt - 14) * 64 * HIDDEN;
        bias = bk + (nt - 14) * 64;
    } else {
        Bhi = (const uint16_t*)g_wvhi + (size_t)(nt - 16) * 64 * HIDDEN;
        Blo = (const uint16_t*)g_wvlo + (size_t)(nt - 16) * 64 * HIDDEN;
        bias = bv + (nt - 16) * 64;
    }

    float c[2][8][4];
    gemm3_core((const uint16_t*)g_xhi, (const uint16_t*)g_xlo, Bhi, Blo, m0, c, smem, tid);

#pragma unroll
    for (int mg = 0; mg < 2; mg++) {
#pragma unroll
        for (int rr = 0; rr < 2; rr++) {
            int row = m0 + w * 32 + mg * 16 + lg + rr * 8;   // token index
            int b = row >> 11;
            int s = row & (S - 1);
            if (nt < 16) {
                const bool isQ = (nt < 14);
                float* base = isQ
                    ? qo + (((size_t)b * NH + nt) * S + s) * HD
                    : ko + (((size_t)b * NKV + (nt - 14)) * S + s) * HD;
                const float sc = isQ ? ASCALE : 1.0f;
#pragma unroll
                for (int nf = 0; nf < 4; nf++) {
                    int d0 = nf * 8 + 2 * lt;
                    float2 t0 = rope[s * 32 + d0];
                    float2 t1 = rope[s * 32 + d0 + 1];
                    float x10 = c[mg][nf][rr * 2 + 0] + bias[d0];
                    float x11 = c[mg][nf][rr * 2 + 1] + bias[d0 + 1];
                    float x20 = c[mg][nf + 4][rr * 2 + 0] + bias[d0 + 32];
                    float x21 = c[mg][nf + 4][rr * 2 + 1] + bias[d0 + 33];
                    float y10 = (x10 * t0.x - x20 * t0.y) * sc;
                    float y11 = (x11 * t1.x - x21 * t1.y) * sc;
                    float y20 = (x20 * t0.x + x10 * t0.y) * sc;
                    float y21 = (x21 * t1.x + x11 * t1.y) * sc;
                    *reinterpret_cast<float2*>(base + d0) =
                        make_float2(__uint_as_float(f2tf32(y10)), __uint_as_float(f2tf32(y11)));
                    *reinterpret_cast<float2*>(base + d0 + 32) =
                        make_float2(__uint_as_float(f2tf32(y20)), __uint_as_float(f2tf32(y21)));
                }
            } else {
                // V transposed: [b][kv][d][s]
                float* base = vt + ((size_t)(b * NKV + (nt - 16)) * HD) * S + s;
#pragma unroll
                for (int nf = 0; nf < 8; nf++) {
                    int d0 = nf * 8 + 2 * lt;
                    base[(size_t)d0 * S] =
                        __uint_as_float(f2tf32(c[mg][nf][rr * 2 + 0] + bias[d0]));
                    base[(size_t)(d0 + 1) * S] =
                        __uint_as_float(f2tf32(c[mg][nf][rr * 2 + 1] + bias[d0 + 1]));
                }
            }
        }
    }
}

// ---- output projection: d_out = attn * Wo^T ----
__global__ __launch_bounds__(128) void gemm_out(float* __restrict__ C) {
    extern __shared__ char smem[];
    const int tid = threadIdx.x;
    const int w = tid >> 5;
    const int lane = tid & 31;
    const int lg = lane >> 2;
    const int lt = lane & 3;
    const int n0 = blockIdx.x * 64;
    const int m0 = blockIdx.y * 128;

    float c[2][8][4];
    gemm3_core((const uint16_t*)g_ahi, (const uint16_t*)g_alo,
               (const uint16_t*)g_wohi + (size_t)n0 * HIDDEN,
               (const uint16_t*)g_wolo + (size_t)n0 * HIDDEN,
               m0, c, smem, tid);

#pragma unroll
    for (int mg = 0; mg < 2; mg++) {
        const int row = m0 + w * 32 + mg * 16 + lg;
#pragma unroll
        for (int nf = 0; nf < 8; nf++) {
            int col = n0 + nf * 8 + 2 * lt;
            *reinterpret_cast<float2*>(&C[(size_t)row * HIDDEN + col]) =
                make_float2(c[mg][nf][0], c[mg][nf][1]);
            *reinterpret_cast<float2*>(&C[(size_t)(row + 8) * HIDDEN + col]) =
                make_float2(c[mg][nf][2], c[mg][nf][3]);
        }
    }
}

// ---------------- Flash attention: tf32 mma, 64 q/CTA, 128 thr, 3 CTAs/SM ------
#define AST 68
#define ATILE (64 * AST)                       // words per K or Vt tile
#define ATTN_SMEM ((2 * ATILE + 64 * AST) * 4) // K + Vt + P = 52224 B

__global__ __launch_bounds__(128, 3) void attn_kernel(const float* __restrict__ Q,
                                                      const float* __restrict__ K,
                                                      const float* __restrict__ V,   // [d][s]
                                                      uint32_t* __restrict__ Ohi,
                                                      uint32_t* __restrict__ Olo) {
    extern __shared__ uint32_t sm_u[];
    uint32_t* Ps = sm_u + 2 * ATILE;           // [64][68]

    const uint32_t sbase = (uint32_t)__cvta_generic_to_shared(sm_u);
    const uint32_t kb = sbase;
    const uint32_t vb = sbase + ATILE * 4;
    const uint32_t ps_b = sbase + 2 * ATILE * 4;

    const int qt = gridDim.x - 1 - blockIdx.x;  // heavy tiles launch first
    const int h = blockIdx.y;
    const int b = blockIdx.z;
    const int kvh = h / NREP;
    const int tid = threadIdx.x;
    const int w = tid >> 5;                     // 4 warps
    const int lane = tid & 31;
    const int lg = lane >> 2;
    const int lt = lane & 3;

    const float* Qb = Q + (((size_t)b * NH + h) * S + (size_t)qt * 64) * HD;
    const float* Kb = K + (((size_t)b * NKV + kvh) * S) * HD;
    const float* Vtb = V + ((size_t)(b * NKV + kvh) * HD) * S;

    // Q fragments (pre-scaled, tf32-rounded at projection)
    uint32_t aq[8][4];
    {
        const int r0 = w * 16 + lg;
#pragma unroll
        for (int ks = 0; ks < 8; ks++) {
            int c0 = ks * 8 + lt;
            aq[ks][0] = __float_as_uint(Qb[(size_t)r0 * HD + c0]);
            aq[ks][1] = __float_as_uint(Qb[(size_t)(r0 + 8) * HD + c0]);
            aq[ks][2] = __float_as_uint(Qb[(size_t)r0 * HD + c0 + 4]);
            aq[ks][3] = __float_as_uint(Qb[(size_t)(r0 + 8) * HD + c0 + 4]);
        }
    }

    const int k_row = ((lane >> 4) << 3) + (lane & 7);
    const int k_col = ((lane >> 3) & 1) << 2;            // words
    const int p_row = w * 16 + (lane & 15);
    const int p_col = (lane >> 4) << 2;

    float o[8][4];
#pragma unroll
    for (int n = 0; n < 8; n++)
#pragma unroll
        for (int j = 0; j < 4; j++) o[n][j] = 0.f;
    float m0 = -1e30f, m1 = -1e30f, l0 = 0.f, l1 = 0.f;

    for (int kt = 0; kt <= qt; kt++) {
        __syncthreads();
        // stage K,V tiles (single buffer; cross-CTA overlap hides latency)
#pragma unroll
        for (int i = tid; i < 2048; i += 128) {
            int isV = i >> 10;
            int idx = i & 1023;
            int r = idx >> 4;
            int cw = (idx & 15) * 4;
            if (isV) {
                CP_ASYNC16(vb + (uint32_t)((r * AST + cw) * 4),
                           Vtb + (size_t)r * S + (size_t)kt * 64 + cw);
            } else {
                CP_ASYNC16(kb + (uint32_t)((r * AST + cw) * 4),
                           Kb + ((size_t)kt * 64 + r) * HD + cw);
            }
        }
        CP_COMMIT();
        CP_WAIT(0);
        __syncthreads();

        // ---- QK^T ----
        float c[8][4];
#pragma unroll
        for (int n = 0; n < 8; n++)
#pragma unroll
            for (int j = 0; j < 4; j++) c[n][j] = 0.f;
#pragma unroll
        for (int ks = 0; ks < 8; ks++) {
#pragma unroll
            for (int jp = 0; jp < 4; jp++) {
                uint32_t kb0, kb1, kb2, kb3;
                uint32_t addr = kb + (uint32_t)(((jp * 16 + k_row) * AST + ks * 8 + k_col) * 4);
                LDSM_X4(kb0, kb1, kb2, kb3, addr);
                mma_tf32(c[2 * jp], aq[ks], kb0, kb1);
                mma_tf32(c[2 * jp + 1], aq[ks], kb2, kb3);
            }
        }

        if (kt == qt) {
            const int row0 = qt * 64 + w * 16 + lg;
#pragma unroll
            for (int n = 0; n < 8; n++) {
                int col = kt * 64 + n * 8 + 2 * lt;
                if (col > row0)         c[n][0] = -1e30f;
                if (col + 1 > row0)     c[n][1] = -1e30f;
                if (col > row0 + 8)     c[n][2] = -1e30f;
                if (col + 1 > row0 + 8) c[n][3] = -1e30f;
            }
        }

        // ---- online softmax (log2 domain) ----
        float mx0 = -1e30f, mx1 = -1e30f;
#pragma unroll
        for (int n = 0; n < 8; n++) {
            mx0 = fmaxf(mx0, fmaxf(c[n][0], c[n][1]));
            mx1 = fmaxf(mx1, fmaxf(c[n][2], c[n][3]));
        }
        mx0 = fmaxf(mx0, __shfl_xor_sync(0xffffffffu, mx0, 1));
        mx0 = fmaxf(mx0, __shfl_xor_sync(0xffffffffu, mx0, 2));
        mx1 = fmaxf(mx1, __shfl_xor_sync(0xffffffffu, mx1, 1));
        mx1 = fmaxf(mx1, __shfl_xor_sync(0xffffffffu, mx1, 2));

        float mn0 = fmaxf(m0, mx0);
        float mn1 = fmaxf(m1, mx1);
        float corr0 = exp2f(m0 - mn0);
        float corr1 = exp2f(m1 - mn1);

        float sum0 = 0.f, sum1 = 0.f;
        {
            const int r0 = w * 16 + lg;
            uint32_t* p0row = Ps + r0 * AST + 2 * lt;
            uint32_t* p1row = Ps + (r0 + 8) * AST + 2 * lt;
#pragma unroll
            for (int n = 0; n < 8; n++) {
                float p00 = exp2f(c[n][0] - mn0);
                float p01 = exp2f(c[n][1] - mn0);
                float p10 = exp2f(c[n][2] - mn1);
                float p11 = exp2f(c[n][3] - mn1);
                sum0 += p00 + p01;
                sum1 += p10 + p11;
                *reinterpret_cast<uint2*>(p0row + n * 8) = make_uint2(f2tf32(p00), f2tf32(p01));
                *reinterpret_cast<uint2*>(p1row + n * 8) = make_uint2(f2tf32(p10), f2tf32(p11));
            }
        }
        sum0 += __shfl_xor_sync(0xffffffffu, sum0, 1);
        sum0 += __shfl_xor_sync(0xffffffffu, sum0, 2);
        sum1 += __shfl_xor_sync(0xffffffffu, sum1, 1);
        sum1 += __shfl_xor_sync(0xffffffffu, sum1, 2);

        l0 = l0 * corr0 + sum0;
        l1 = l1 * corr1 + sum1;
        m0 = mn0;
        m1 = mn1;

#pragma unroll
        for (int n = 0; n < 8; n++) {
            o[n][0] *= corr0;
            o[n][1] *= corr0;
            o[n][2] *= corr1;
            o[n][3] *= corr1;
        }
        __syncwarp();

        // ---- P*V (Vt staged [d][key]) ----
#pragma unroll
        for (int ks = 0; ks < 8; ks++) {
            uint32_t pa[4];
            uint32_t paddr = ps_b + (uint32_t)((p_row * AST + ks * 8 + p_col) * 4);
            LDSM_X4(pa[0], pa[1], pa[2], pa[3], paddr);
#pragma unroll
            for (int jp = 0; jp < 4; jp++) {
                uint32_t v0, v1, v2, v3;
                uint32_t addr = vb + (uint32_t)(((jp * 16 + k_row) * AST + ks * 8 + k_col) * 4);
                LDSM_X4(v0, v1, v2, v3, addr);
                mma_tf32(o[2 * jp], pa, v0, v1);
                mma_tf32(o[2 * jp + 1], pa, v2, v3);
            }
        }
    }

    // ---- write normalized output as bf16 hi/lo ----
    {
        float inv0 = 1.f / l0;
        float inv1 = 1.f / l1;
        const int r0 = qt * 64 + w * 16 + lg;
        size_t base0 = ((size_t)b * S + r0) * HIDDEN + h * HD + 2 * lt;
        size_t base1 = ((size_t)b * S + r0 + 8) * HIDDEN + h * HD + 2 * lt;
#pragma unroll
        for (int n = 0; n < 8; n++) {
            uint32_t hi, lo;
            split2(o[n][0] * inv0, o[n][1] * inv0, hi, lo);
            Ohi[(base0 + n * 8) >> 1] = hi;
            Olo[(base0 + n * 8) >> 1] = lo;
            split2(o[n][2] * inv1, o[n][3] * inv1, hi, lo);
            Ohi[(base1 + n * 8) >> 1] = hi;
            Olo[(base1 + n * 8) >> 1] = lo;
        }
    }
}

// ---------------- launch ----------------
extern "C" void kernel_launch(void* const* d_in, const int* in_sizes, int n_in,
                              void* d_out, int out_size) {
    const float* hs = (const float*)d_in[0];
    const float* Wq = (const float*)d_in[2];
    const float* bq = (const float*)d_in[3];
    const float* Wk = (const float*)d_in[4];
    const float* bk = (const float*)d_in[5];
    const float* Wv = (const float*)d_in[6];
    const float* bv = (const float*)d_in[7];
    const float* Wo = (const float*)d_in[8];
    float* out = (float*)d_out;

    float *q, *k, *vt;
    float2* rope;
    uint2 *ahi, *alo;
    cudaGetSymbolAddress((void**)&q, g_q);
    cudaGetSymbolAddress((void**)&k, g_k);
    cudaGetSymbolAddress((void**)&vt, g_vt);
    cudaGetSymbolAddress((void**)&rope, g_rope);
    cudaGetSymbolAddress((void**)&ahi, g_ahi);
    cudaGetSymbolAddress((void**)&alo, g_alo);

    static bool attr_set = false;
    if (!attr_set) {
        cudaFuncSetAttribute(attn_kernel, cudaFuncAttributeMaxDynamicSharedMemorySize, ATTN_SMEM);
        cudaFuncSetAttribute(gemm_qkv, cudaFuncAttributeMaxDynamicSharedMemorySize, GEMM_SMEM);
        cudaFuncSetAttribute(gemm_out, cudaFuncAttributeMaxDynamicSharedMemorySize, GEMM_SMEM);
        attr_set = true;
    }

    build_rope<<<(S * 32) / 256, 256>>>(rope);
    conv_split<<<(TOT4 + 255) / 256, 256>>>((const float4*)hs, (const float4*)Wq,
                                            (const float4*)Wk, (const float4*)Wv,
                                            (const float4*)Wo);

    gemm_qkv<<<dim3(18, MTOK / 128), 128, GEMM_SMEM>>>(bq, bk, bv, rope, q, k, vt);

    attn_kernel<<<dim3(S / 64, NH, B), 128, ATTN_SMEM>>>(q, k, vt,
                                                         (uint32_t*)ahi, (uint32_t*)alo);

    gemm_out<<<dim3(HIDDEN / 64, MTOK / 128), 128, GEMM_SMEM>>>(out);
}

// round 9
// speedup vs baseline: 4.4706x; 1.0147x over previous
#include <cuda_runtime.h>
#include <cuda_bf16.h>
#include <cstdint>

#define B 2
#define S 2048
#define HIDDEN 896
#define NH 14
#define NKV 2
#define HD 64
#define NREP 7
#define MTOK (B*S)          // 4096 tokens

// element counts (float4 units)
#define NX4  (MTOK*HIDDEN/4)        // 917504
#define NQ4  (HIDDEN*HIDDEN/4)      // 200704
#define NK4  (NKV*HD*HIDDEN/4)      // 28672
#define NV4  NK4
#define NO4  NQ4
#define TOT4 (NX4 + NQ4 + NK4 + NV4 + NO4)   // 1376256

// ---------------- scratch (device globals) ----------------
__device__ float g_q[B * NH * S * HD];         // [b,h,s,d]  (pre-scaled, tf32-rounded)
__device__ float g_k[B * NKV * S * HD];        // [b,kv,s,d] (tf32-rounded)
__device__ float g_vt[B * NKV * HD * S];       // [b,kv,d,s] TRANSPOSED (tf32-rounded)
__device__ float2 g_rope[S * 32];

// bf16 hi/lo pre-converted operands (uint2 = 4 bf16)
__device__ uint2 g_xhi[NX4],  g_xlo[NX4];      // hidden_states
__device__ uint2 g_wqhi[NQ4], g_wqlo[NQ4];
__device__ uint2 g_wkhi[NK4], g_wklo[NK4];
__device__ uint2 g_wvhi[NV4], g_wvlo[NV4];
__device__ uint2 g_wohi[NO4], g_wolo[NO4];
__device__ uint2 g_ahi[NX4],  g_alo[NX4];      // attention output

// Q pre-scale: 1/sqrt(64) * log2(e)
#define ASCALE 0.1803368801111204f

// ---------------- helpers ----------------
__device__ __forceinline__ uint32_t f2tf32(float x) {
    uint32_t r;
    asm("cvt.rna.tf32.f32 %0, %1;" : "=r"(r) : "f"(x));
    return r;
}

__device__ __forceinline__ void mma_tf32(float* d, const uint32_t* a, uint32_t b0, uint32_t b1) {
    asm volatile(
        "mma.sync.aligned.m16n8k8.row.col.f32.tf32.tf32.f32 "
        "{%0,%1,%2,%3}, {%4,%5,%6,%7}, {%8,%9}, {%0,%1,%2,%3};\n"
        : "+f"(d[0]), "+f"(d[1]), "+f"(d[2]), "+f"(d[3])
        : "r"(a[0]), "r"(a[1]), "r"(a[2]), "r"(a[3]), "r"(b0), "r"(b1));
}

__device__ __forceinline__ void mma_bf16(float* d, const uint32_t* a, uint32_t b0, uint32_t b1) {
    asm volatile(
        "mma.sync.aligned.m16n8k16.row.col.f32.bf16.bf16.f32 "
        "{%0,%1,%2,%3}, {%4,%5,%6,%7}, {%8,%9}, {%0,%1,%2,%3};\n"
        : "+f"(d[0]), "+f"(d[1]), "+f"(d[2]), "+f"(d[3])
        : "r"(a[0]), "r"(a[1]), "r"(a[2]), "r"(a[3]), "r"(b0), "r"(b1));
}

#define LDSM_X4(r0, r1, r2, r3, addr) \
    asm volatile("ldmatrix.sync.aligned.m8n8.x4.shared.b16 {%0,%1,%2,%3}, [%4];" \
                 : "=r"(r0), "=r"(r1), "=r"(r2), "=r"(r3) : "r"(addr))

#define CP_ASYNC16(dst, src) \
    asm volatile("cp.async.ca.shared.global [%0], [%1], 16;" :: "r"(dst), "l"(src))
#define CP_COMMIT() asm volatile("cp.async.commit_group;" ::: "memory")
#define CP_WAIT(n)  asm volatile("cp.async.wait_group %0;" :: "n"(n) : "memory")

// pack two floats into bf16x2 hi word + bf16x2 lo (residual) word
__device__ __forceinline__ void split2(float x0, float x1, uint32_t& hi, uint32_t& lo) {
    asm("cvt.rn.bf16x2.f32 %0, %1, %2;" : "=r"(hi) : "f"(x1), "f"(x0));
    float h0 = __uint_as_float(hi << 16);
    float h1 = __uint_as_float(hi & 0xffff0000u);
    float r0 = x0 - h0;
    float r1 = x1 - h1;
    asm("cvt.rn.bf16x2.f32 %0, %1, %2;" : "=r"(lo) : "f"(r1), "f"(r0));
}

// ---------------- conversion pass: fp32 -> bf16 hi/lo ----------------
__global__ void conv_split(const float4* __restrict__ x,
                           const float4* __restrict__ wq,
                           const float4* __restrict__ wk,
                           const float4* __restrict__ wv,
                           const float4* __restrict__ wo) {
    int i = blockIdx.x * blockDim.x + threadIdx.x;
    if (i >= TOT4) return;
    const float4* src;
    uint2 *hi, *lo;
    int off = i;
    if (off < NX4)                    { src = x;  hi = g_xhi;  lo = g_xlo; }
    else if ((off -= NX4) < NQ4)      { src = wq; hi = g_wqhi; lo = g_wqlo; }
    else if ((off -= NQ4) < NK4)      { src = wk; hi = g_wkhi; lo = g_wklo; }
    else if ((off -= NK4) < NV4)      { src = wv; hi = g_wvhi; lo = g_wvlo; }
    else { off -= NV4;                  src = wo; hi = g_wohi; lo = g_wolo; }
    float4 v = src[off];
    uint2 h, l;
    split2(v.x, v.y, h.x, l.x);
    split2(v.z, v.w, h.y, l.y);
    hi[off] = h;
    lo[off] = l;
}

// ---------------- rope table ----------------
__global__ void build_rope(float2* tab) {
    int idx = blockIdx.x * blockDim.x + threadIdx.x;   // [0, S*32)
    int s = idx >> 5, i = idx & 31;
    const float LOG2_THETA_OVER_32 = 0.62286105580517513f;  // log2(1e6)/32
    float inv = exp2f(-(float)i * LOG2_THETA_OVER_32);
    float sn, cs;
    sincosf((float)s * inv, &sn, &cs);
    tab[idx] = make_float2(cs, sn);
}

// ---------------- GEMM core: pre-split bf16, CTA 128x64, 128 thr, BK=32 ----------
#define XH_OFF 0
#define XL_OFF 10240
#define WH_OFF 20480
#define WL_OFF 25600
#define GBUF   30720
#define GEMM_SMEM (2 * GBUF)
#define NKCH (HIDDEN / 32)     // 28

__device__ __forceinline__ void gemm3_core(const uint16_t* __restrict__ Ahi,
                                           const uint16_t* __restrict__ Alo,
                                           const uint16_t* __restrict__ Bhi,
                                           const uint16_t* __restrict__ Blo,
                                           int m0, float c[2][8][4],
                                           char* smem, int tid) {
    const int w = tid >> 5;
    const int lane = tid & 31;
    const uint32_t sb = (uint32_t)__cvta_generic_to_shared(smem);

    const int arow = (lane & 7) + ((lane >> 3) & 1) * 8;
    const int acol = (lane >> 4) * 16;                    // bytes
    const int brow = (lane & 7) + ((lane >> 4) & 1) * 8;
    const int bcol = ((lane >> 3) & 1) * 16;              // bytes

#pragma unroll
    for (int mg = 0; mg < 2; mg++)
#pragma unroll
        for (int nf = 0; nf < 8; nf++)
#pragma unroll
            for (int j = 0; j < 4; j++) c[mg][nf][j] = 0.f;

    auto stage = [&](int kc, int buf) {
        int k0 = kc * 32;
        uint32_t base = sb + buf * GBUF;
#pragma unroll
        for (int t = 0; t < 4; t++) {
            int i = tid + t * 128;
            int row = i >> 2, c16 = i & 3;
            size_t so = ((size_t)(m0 + row) * HIDDEN + k0) * 2 + c16 * 16;
            uint32_t d = base + row * 80 + c16 * 16;
            CP_ASYNC16(d + XH_OFF, (const char*)Ahi + so);
            CP_ASYNC16(d + XL_OFF, (const char*)Alo + so);
        }
#pragma unroll
        for (int t = 0; t < 2; t++) {
            int i = tid + t * 128;
            int row = i >> 2, c16 = i & 3;
            size_t so = ((size_t)row * HIDDEN + k0) * 2 + c16 * 16;
            uint32_t d = base + row * 80 + c16 * 16;
            CP_ASYNC16(d + WH_OFF, (const char*)Bhi + so);
            CP_ASYNC16(d + WL_OFF, (const char*)Blo + so);
        }
    };

    stage(0, 0);
    CP_COMMIT();

    for (int kc = 0; kc < NKCH; kc++) {
        if (kc + 1 < NKCH) {
            stage(kc + 1, (kc + 1) & 1);
            CP_COMMIT();
            CP_WAIT(1);
        } else {
            CP_WAIT(0);
        }
        __syncthreads();

        uint32_t base = sb + (kc & 1) * GBUF;
#pragma unroll
        for (int ks = 0; ks < 2; ks++) {
            uint32_t ah[2][4], al[2][4];
#pragma unroll
            for (int mg = 0; mg < 2; mg++) {
                uint32_t aaddr = base + XH_OFF + (w * 32 + mg * 16 + arow) * 80 + acol + ks * 32;
                LDSM_X4(ah[mg][0], ah[mg][1], ah[mg][2], ah[mg][3], aaddr);
                LDSM_X4(al[mg][0], al[mg][1], al[mg][2], al[mg][3], aaddr + (XL_OFF - XH_OFF));
            }
#pragma unroll
            for (int np = 0; np < 4; np++) {
                uint32_t baddr = base + WH_OFF + (np * 16 + brow) * 80 + bcol + ks * 32;
                uint32_t bh0, bh1, bh2, bh3, bl0, bl1, bl2, bl3;
                LDSM_X4(bh0, bh1, bh2, bh3, baddr);
                LDSM_X4(bl0, bl1, bl2, bl3, baddr + (WL_OFF - WH_OFF));
#pragma unroll
                for (int mg = 0; mg < 2; mg++) {
                    mma_bf16(c[mg][2 * np],     ah[mg], bh0, bh1);
                    mma_bf16(c[mg][2 * np],     ah[mg], bl0, bl1);
                    mma_bf16(c[mg][2 * np],     al[mg], bh0, bh1);
                    mma_bf16(c[mg][2 * np + 1], ah[mg], bh2, bh3);
                    mma_bf16(c[mg][2 * np + 1], ah[mg], bl2, bl3);
                    mma_bf16(c[mg][2 * np + 1], al[mg], bh2, bh3);
                }
            }
        }
        __syncthreads();
    }
}

// ---- fused QKV projection + bias + RoPE + transpose ----
__global__ __launch_bounds__(128) void gemm_qkv(const float* __restrict__ bq,
                                                const float* __restrict__ bk,
                                                const float* __restrict__ bv,
                                                const float2* __restrict__ rope,
                                                float* __restrict__ qo,
                                                float* __restrict__ ko,
                                                float* __restrict__ vt) {
    extern __shared__ char smem[];
    const int tid = threadIdx.x;
    const int w = tid >> 5;
    const int lane = tid & 31;
    const int lg = lane >> 2;
    const int lt = lane & 3;
    const int nt = blockIdx.x;
    const int m0 = blockIdx.y * 128;

    const uint16_t *Bhi, *Blo;
    const float* bias;
    if (nt < 14) {
        Bhi = (const uint16_t*)g_wqhi + (size_t)nt * 64 * HIDDEN;
        Blo = (const uint16_t*)g_wqlo + (size_t)nt * 64 * HIDDEN;
        bias = bq + nt * 64;
    } else if (nt < 16) {
        Bhi = (const uint16_t*)g_wkhi + (size_t)(nt - 14) * 64 * HIDDEN;
        Blo = (const uint16_t*)g_wklo + (size_t)(nt - 14) * 64 * HIDDEN;
        bias = bk + (nt - 14) * 64;
    } else {
        Bhi = (const uint16_t*)g_wvhi + (size_t)(nt - 16) * 64 * HIDDEN;
        Blo = (const uint16_t*)g_wvlo + (size_t)(nt - 16) * 64 * HIDDEN;
        bias = bv + (nt - 16) * 64;
    }

    float c[2][8][4];
    gemm3_core((const uint16_t*)g_xhi, (const uint16_t*)g_xlo, Bhi, Blo, m0, c, smem, tid);

#pragma unroll
    for (int mg = 0; mg < 2; mg++) {
#pragma unroll
        for (int rr = 0; rr < 2; rr++) {
            int row = m0 + w * 32 + mg * 16 + lg + rr * 8;   // token index
            int b = row >> 11;
            int s = row & (S - 1);
            if (nt < 16) {
                const bool isQ = (nt < 14);
                float* base = isQ
                    ? qo + (((size_t)b * NH + nt) * S + s) * HD
                    : ko + (((size_t)b * NKV + (nt - 14)) * S + s) * HD;
                const float sc = isQ ? ASCALE : 1.0f;
#pragma unroll
                for (int nf = 0; nf < 4; nf++) {
                    int d0 = nf * 8 + 2 * lt;
                    float2 t0 = rope[s * 32 + d0];
                    float2 t1 = rope[s * 32 + d0 + 1];
                    float x10 = c[mg][nf][rr * 2 + 0] + bias[d0];
                    float x11 = c[mg][nf][rr * 2 + 1] + bias[d0 + 1];
                    float x20 = c[mg][nf + 4][rr * 2 + 0] + bias[d0 + 32];
                    float x21 = c[mg][nf + 4][rr * 2 + 1] + bias[d0 + 33];
                    float y10 = (x10 * t0.x - x20 * t0.y) * sc;
                    float y11 = (x11 * t1.x - x21 * t1.y) * sc;
                    float y20 = (x20 * t0.x + x10 * t0.y) * sc;
                    float y21 = (x21 * t1.x + x11 * t1.y) * sc;
                    *reinterpret_cast<float2*>(base + d0) =
                        make_float2(__uint_as_float(f2tf32(y10)), __uint_as_float(f2tf32(y11)));
                    *reinterpret_cast<float2*>(base + d0 + 32) =
                        make_float2(__uint_as_float(f2tf32(y20)), __uint_as_float(f2tf32(y21)));
                }
            } else {
                // V transposed: [b][kv][d][s]
                float* base = vt + ((size_t)(b * NKV + (nt - 16)) * HD) * S + s;
#pragma unroll
                for (int nf = 0; nf < 8; nf++) {
                    int d0 = nf * 8 + 2 * lt;
                    base[(size_t)d0 * S] =
                        __uint_as_float(f2tf32(c[mg][nf][rr * 2 + 0] + bias[d0]));
                    base[(size_t)(d0 + 1) * S] =
                        __uint_as_float(f2tf32(c[mg][nf][rr * 2 + 1] + bias[d0 + 1]));
                }
            }
        }
    }
}

// ---- output projection: d_out = attn * Wo^T ----
__global__ __launch_bounds__(128) void gemm_out(float* __restrict__ C) {
    extern __shared__ char smem[];
    const int tid = threadIdx.x;
    const int w = tid >> 5;
    const int lane = tid & 31;
    const int lg = lane >> 2;
    const int lt = lane & 3;
    const int n0 = blockIdx.x * 64;
    const int m0 = blockIdx.y * 128;

    float c[2][8][4];
    gemm3_core((const uint16_t*)g_ahi, (const uint16_t*)g_alo,
               (const uint16_t*)g_wohi + (size_t)n0 * HIDDEN,
               (const uint16_t*)g_wolo + (size_t)n0 * HIDDEN,
               m0, c, smem, tid);

#pragma unroll
    for (int mg = 0; mg < 2; mg++) {
        const int row = m0 + w * 32 + mg * 16 + lg;
#pragma unroll
        for (int nf = 0; nf < 8; nf++) {
            int col = n0 + nf * 8 + 2 * lt;
            *reinterpret_cast<float2*>(&C[(size_t)row * HIDDEN + col]) =
                make_float2(c[mg][nf][0], c[mg][nf][1]);
            *reinterpret_cast<float2*>(&C[(size_t)(row + 8) * HIDDEN + col]) =
                make_float2(c[mg][nf][2], c[mg][nf][3]);
        }
    }
}

// -------- Flash attention: pipelined tf32 mma, 64 q/CTA, double-buffered K/V ----
// Per iter: stage(kt+1) -> softmax(kt) -> QK(kt+1) -> PV(kt): mma fills softmax window.
#define AST 68
#define ATILE (64 * AST)                       // words per K or Vt tile
// layout: K0 | V0 | K1 | V1 | P
#define ATTN_SMEM ((4 * ATILE + 64 * AST) * 4) // 87040 B -> 2 CTAs/SM

__global__ __launch_bounds__(128, 2) void attn_kernel(const float* __restrict__ Q,
                                                      const float* __restrict__ K,
                                                      const float* __restrict__ V,   // [d][s]
                                                      uint32_t* __restrict__ Ohi,
                                                      uint32_t* __restrict__ Olo) {
    extern __shared__ uint32_t sm_u[];
    uint32_t* Ps = sm_u + 4 * ATILE;           // [64][68]

    const uint32_t sbase = (uint32_t)__cvta_generic_to_shared(sm_u);
    const uint32_t ps_b = sbase + 4 * ATILE * 4;

    const int qt = gridDim.x - 1 - blockIdx.x;  // heavy tiles launch first
    const int h = blockIdx.y;
    const int b = blockIdx.z;
    const int kvh = h / NREP;
    const int tid = threadIdx.x;
    const int w = tid >> 5;                     // 4 warps
    const int lane = tid & 31;
    const int lg = lane >> 2;
    const int lt = lane & 3;

    const float* Qb = Q + (((size_t)b * NH + h) * S + (size_t)qt * 64) * HD;
    const float* Kb = K + (((size_t)b * NKV + kvh) * S) * HD;
    const float* Vtb = V + ((size_t)(b * NKV + kvh) * HD) * S;

    // Q fragments (pre-scaled, tf32-rounded at projection)
    uint32_t aq[8][4];
    {
        const int r0 = w * 16 + lg;
#pragma unroll
        for (int ks = 0; ks < 8; ks++) {
            int c0 = ks * 8 + lt;
            aq[ks][0] = __float_as_uint(Qb[(size_t)r0 * HD + c0]);
            aq[ks][1] = __float_as_uint(Qb[(size_t)(r0 + 8) * HD + c0]);
            aq[ks][2] = __float_as_uint(Qb[(size_t)r0 * HD + c0 + 4]);
            aq[ks][3] = __float_as_uint(Qb[(size_t)(r0 + 8) * HD + c0 + 4]);
        }
    }

    const int k_row = ((lane >> 4) << 3) + (lane & 7);
    const int k_col = ((lane >> 3) & 1) << 2;            // words
    const int p_row = w * 16 + (lane & 15);
    const int p_col = (lane >> 4) << 2;

    float o[8][4];
    float c[8][4];
#pragma unroll
    for (int n = 0; n < 8; n++)
#pragma unroll
        for (int j = 0; j < 4; j++) o[n][j] = 0.f;
    float m0 = -1e30f, m1 = -1e30f, l0 = 0.f, l1 = 0.f;

    auto stage = [&](int kt, int buf) {
        uint32_t kb = sbase + (2 * buf) * ATILE * 4;
        uint32_t vb = sbase + (2 * buf + 1) * ATILE * 4;
#pragma unroll
        for (int i = tid; i < 2048; i += 128) {
            int isV = i >> 10;
            int idx = i & 1023;
            int r = idx >> 4;
            int cw = (idx & 15) * 4;
            if (isV) {
                CP_ASYNC16(vb + (uint32_t)((r * AST + cw) * 4),
                           Vtb + (size_t)r * S + (size_t)kt * 64 + cw);
            } else {
                CP_ASYNC16(kb + (uint32_t)((r * AST + cw) * 4),
                           Kb + ((size_t)kt * 64 + r) * HD + cw);
            }
        }
    };

    auto qk_compute = [&](int buf) {
        uint32_t kb = sbase + (2 * buf) * ATILE * 4;
#pragma unroll
        for (int n = 0; n < 8; n++)
#pragma unroll
            for (int j = 0; j < 4; j++) c[n][j] = 0.f;
#pragma unroll
        for (int ks = 0; ks < 8; ks++) {
#pragma unroll
            for (int jp = 0; jp < 4; jp++) {
                uint32_t kb0, kb1, kb2, kb3;
                uint32_t addr = kb + (uint32_t)(((jp * 16 + k_row) * AST + ks * 8 + k_col) * 4);
                LDSM_X4(kb0, kb1, kb2, kb3, addr);
                mma_tf32(c[2 * jp], aq[ks], kb0, kb1);
                mma_tf32(c[2 * jp + 1], aq[ks], kb2, kb3);
            }
        }
    };

    auto pv_compute = [&](int buf) {
        uint32_t vb = sbase + (2 * buf + 1) * ATILE * 4;
#pragma unroll
        for (int ks = 0; ks < 8; ks++) {
            uint32_t pa[4];
            uint32_t paddr = ps_b + (uint32_t)((p_row * AST + ks * 8 + p_col) * 4);
            LDSM_X4(pa[0], pa[1], pa[2], pa[3], paddr);
#pragma unroll
            for (int jp = 0; jp < 4; jp++) {
                uint32_t v0, v1, v2, v3;
                uint32_t addr = vb + (uint32_t)(((jp * 16 + k_row) * AST + ks * 8 + k_col) * 4);
                LDSM_X4(v0, v1, v2, v3, addr);
                mma_tf32(o[2 * jp], pa, v0, v1);
                mma_tf32(o[2 * jp + 1], pa, v2, v3);
            }
        }
    };

    // prologue: stage tile 0, QK(0)
    stage(0, 0);
    CP_COMMIT();
    CP_WAIT(0);
    __syncthreads();
    qk_compute(0);

    for (int kt = 0; kt <= qt; kt++) {
        const int cur = kt & 1;
        const bool more = (kt < qt);
        if (more) {
            stage(kt + 1, cur ^ 1);
            CP_COMMIT();
        }

        // ---- causal mask on diagonal tile ----
        if (kt == qt) {
            const int row0 = qt * 64 + w * 16 + lg;
#pragma unroll
            for (int n = 0; n < 8; n++) {
                int col = kt * 64 + n * 8 + 2 * lt;
                if (col > row0)         c[n][0] = -1e30f;
                if (col + 1 > row0)     c[n][1] = -1e30f;
                if (col > row0 + 8)     c[n][2] = -1e30f;
                if (col + 1 > row0 + 8) c[n][3] = -1e30f;
            }
        }

        // ---- online softmax (log2 domain), P -> smem (tf32) ----
        float mx0 = -1e30f, mx1 = -1e30f;
#pragma unroll
        for (int n = 0; n < 8; n++) {
            mx0 = fmaxf(mx0, fmaxf(c[n][0], c[n][1]));
            mx1 = fmaxf(mx1, fmaxf(c[n][2], c[n][3]));
        }
        mx0 = fmaxf(mx0, __shfl_xor_sync(0xffffffffu, mx0, 1));
        mx0 = fmaxf(mx0, __shfl_xor_sync(0xffffffffu, mx0, 2));
        mx1 = fmaxf(mx1, __shfl_xor_sync(0xffffffffu, mx1, 1));
        mx1 = fmaxf(mx1, __shfl_xor_sync(0xffffffffu, mx1, 2));

        float mn0 = fmaxf(m0, mx0);
        float mn1 = fmaxf(m1, mx1);
        float corr0 = exp2f(m0 - mn0);
        float corr1 = exp2f(m1 - mn1);

        float sum0 = 0.f, sum1 = 0.f;
        {
            const int r0 = w * 16 + lg;
            uint32_t* p0row = Ps + r0 * AST + 2 * lt;
            uint32_t* p1row = Ps + (r0 + 8) * AST + 2 * lt;
#pragma unroll
            for (int n = 0; n < 8; n++) {
                float p00 = exp2f(c[n][0] - mn0);
                float p01 = exp2f(c[n][1] - mn0);
                float p10 = exp2f(c[n][2] - mn1);
                float p11 = exp2f(c[n][3] - mn1);
                sum0 += p00 + p01;
                sum1 += p10 + p11;
                *reinterpret_cast<uint2*>(p0row + n * 8) = make_uint2(f2tf32(p00), f2tf32(p01));
                *reinterpret_cast<uint2*>(p1row + n * 8) = make_uint2(f2tf32(p10), f2tf32(p11));
            }
        }
        sum0 += __shfl_xor_sync(0xffffffffu, sum0, 1);
        sum0 += __shfl_xor_sync(0xffffffffu, sum0, 2);
        sum1 += __shfl_xor_sync(0xffffffffu, sum1, 1);
        sum1 += __shfl_xor_sync(0xffffffffu, sum1, 2);

        l0 = l0 * corr0 + sum0;
        l1 = l1 * corr1 + sum1;
        m0 = mn0;
        m1 = mn1;

#pragma unroll
        for (int n = 0; n < 8; n++) {
            o[n][0] *= corr0;
            o[n][1] *= corr0;
            o[n][2] *= corr1;
            o[n][3] *= corr1;
        }
        __syncwarp();

        // ---- QK(kt+1): c regs are free (P in smem); fills softmax latency ----
        if (more) {
            CP_WAIT(0);
            __syncthreads();        // K/V(kt+1) visible to all warps
            qk_compute(cur ^ 1);
        }

        // ---- PV(kt) ----
        pv_compute(cur);
        __syncthreads();            // all warps done with buf cur before restage
    }

    // ---- write normalized output as bf16 hi/lo ----
    {
        float inv0 = 1.f / l0;
        float inv1 = 1.f / l1;
        const int r0 = qt * 64 + w * 16 + lg;
        size_t base0 = ((size_t)b * S + r0) * HIDDEN + h * HD + 2 * lt;
        size_t base1 = ((size_t)b * S + r0 + 8) * HIDDEN + h * HD + 2 * lt;
#pragma unroll
        for (int n = 0; n < 8; n++) {
            uint32_t hi, lo;
            split2(o[n][0] * inv0, o[n][1] * inv0, hi, lo);
            Ohi[(base0 + n * 8) >> 1] = hi;
            Olo[(base0 + n * 8) >> 1] = lo;
            split2(o[n][2] * inv1, o[n][3] * inv1, hi, lo);
            Ohi[(base1 + n * 8) >> 1] = hi;
            Olo[(base1 + n * 8) >> 1] = lo;
        }
    }
}

// ---------------- launch ----------------
extern "C" void kernel_launch(void* const* d_in, const int* in_sizes, int n_in,
                              void* d_out, int out_size) {
    const float* hs = (const float*)d_in[0];
    const float* Wq = (const float*)d_in[2];
    const float* bq = (const float*)d_in[3];
    const float* Wk = (const float*)d_in[4];
    const float* bk = (const float*)d_in[5];
    const float* Wv = (const float*)d_in[6];
    const float* bv = (const float*)d_in[7];
    const float* Wo = (const float*)d_in[8];
    float* out = (float*)d_out;

    float *q, *k, *vt;
    float2* rope;
    uint2 *ahi, *alo;
    cudaGetSymbolAddress((void**)&q, g_q);
    cudaGetSymbolAddress((void**)&k, g_k);
    cudaGetSymbolAddress((void**)&vt, g_vt);
    cudaGetSymbolAddress((void**)&rope, g_rope);
    cudaGetSymbolAddress((void**)&ahi, g_ahi);
    cudaGetSymbolAddress((void**)&alo, g_alo);

    static bool attr_set = false;
    if (!attr_set) {
        cudaFuncSetAttribute(attn_kernel, cudaFuncAttributeMaxDynamicSharedMemorySize, ATTN_SMEM);
        cudaFuncSetAttribute(gemm_qkv, cudaFuncAttributeMaxDynamicSharedMemorySize, GEMM_SMEM);
        cudaFuncSetAttribute(gemm_out, cudaFuncAttributeMaxDynamicSharedMemorySize, GEMM_SMEM);
        attr_set = true;
    }

    build_rope<<<(S * 32) / 256, 256>>>(rope);
    conv_split<<<(TOT4 + 255) / 256, 256>>>((const float4*)hs, (const float4*)Wq,
                                            (const float4*)Wk, (const float4*)Wv,
                                            (const float4*)Wo);

    gemm_qkv<<<dim3(18, MTOK / 128), 128, GEMM_SMEM>>>(bq, bk, bv, rope, q, k, vt);

    attn_kernel<<<dim3(S / 64, NH, B), 128, ATTN_SMEM>>>(q, k, vt,
                                                         (uint32_t*)ahi, (uint32_t*)alo);

    gemm_out<<<dim3(HIDDEN / 64, MTOK / 128), 128, GEMM_SMEM>>>(out);
}